// round 13
// baseline (speedup 1.0000x reference)
#include <cuda_runtime.h>
#include <cuda_bf16.h>

#define TENC 48
#define TDEC 24
#define DSTEPS 30
#define HD 128
#define NF1 17
#define NF2 129
#define K1 145
#define KP1 160
#define K2 257
#define KP2 272
#define KD 256
#define KPD 256
#define G 8
#define GS 4          // batch elements per stage CTA
#define NCTA 128
#define NCTA_S 256
#define NTH 512
#define NG 512
#define BTOT 1024
#define HCT_STR 10    // decoder hcT stride (8 g + 2 pad)
#define HS_STR 6      // stage hcT stride (4 g + 2 pad)

typedef unsigned long long u64;

// ---------------- device scratch (allocation-free) ----------------
__device__ unsigned g_W21[(KP1 / 2) * NG];   // [k/2][n], u32 = bf16(w[2k][n]) | bf16(w[2k+1][n])<<16
__device__ unsigned g_W22[(KP2 / 2) * NG];
__device__ unsigned g_W2d[(KPD / 2) * NG];
__device__ float g_Wet1[256 * TENC];
__device__ float g_Wet2[256 * TENC];
__device__ float g_Wdt[256 * HD];             // [k][j]
__device__ float g_Udt[HD * HD];
__device__ float g_b1[NG], g_b2[NG], g_bd[NG];
__device__ float g_pre1[BTOT * NF1 * TENC];           // [b][f][s] fp32 (TRANSPOSED)
__device__ __nv_bfloat16 g_pre2h[BTOT * NF2 * TENC];  // [b][f][s] bf16 (TRANSPOSED)
__device__ float g_mid[BTOT * TENC * NF2];            // [b][t][f] (f=128 label)
__device__ float g_fin[BTOT * TENC * HD];             // [b][t][j]
__device__ __nv_bfloat16 g_udTh[BTOT * HD * TENC];    // [b][j][t] bf16

// ---------------- math helpers ----------------
__device__ __forceinline__ float tanha(float x) {
    float y; asm("tanh.approx.f32 %0, %1;" : "=f"(y) : "f"(x)); return y;
}
__device__ __forceinline__ float siga(float x) {
    return fmaf(tanha(0.5f * x), 0.5f, 0.5f);
}
__device__ __forceinline__ u64 fma2(u64 a, u64 b, u64 c) {
    u64 d; asm("fma.rn.f32x2 %0, %1, %2, %3;" : "=l"(d) : "l"(a), "l"(b), "l"(c)); return d;
}
__device__ __forceinline__ u64 dup2(float x) {
    u64 d; unsigned r = __float_as_uint(x);
    asm("mov.b64 %0, {%1, %1};" : "=l"(d) : "r"(r)); return d;
}
__device__ __forceinline__ float2 unpack2(u64 a) {
    unsigned l, h;
    asm("mov.b64 {%0, %1}, %2;" : "=r"(l), "=r"(h) : "l"(a));
    return make_float2(__uint_as_float(l), __uint_as_float(h));
}
// bf16-pair -> packed f32x2
__device__ __forceinline__ u64 bf2f2(unsigned w) {
    unsigned lo = w << 16;
    unsigned hi = w & 0xffff0000u;
    u64 d;
    asm("mov.b64 %0, {%1, %2};" : "=l"(d) : "r"(lo), "r"(hi));
    return d;
}
__device__ __forceinline__ void barg(int p) {
    asm volatile("bar.sync %0, %1;" :: "r"(p + 1), "r"(128) : "memory");
}

__device__ __forceinline__ void warp_softmax(const float* score_row, float* alpha_row,
                                             int F, int lane) {
    float mx = -1e30f;
    for (int f = lane; f < F; f += 32) mx = fmaxf(mx, score_row[f]);
#pragma unroll
    for (int o = 16; o; o >>= 1) mx = fmaxf(mx, __shfl_xor_sync(0xffffffffu, mx, o));
    float sm = 0.f;
    for (int f = lane; f < F; f += 32) {
        float e = __expf(score_row[f] - mx);
        alpha_row[f] = e;
        sm += e;
    }
#pragma unroll
    for (int o = 16; o; o >>= 1) sm += __shfl_xor_sync(0xffffffffu, sm, o);
    float inv = __fdividef(1.f, sm);
    for (int f = lane; f < F; f += 32) alpha_row[f] *= inv;
}

__global__ void nop_kernel() {}

// ---- gate GEMM (8-g version, decoder): k-pair packed weights [k/2][n] ----
template <int KP>
__device__ __forceinline__ void gates_gemm5(const unsigned* __restrict__ W2,
                                            const float* __restrict__ bias,
                                            const float* __restrict__ ipT,  // [8][KP]
                                            float* __restrict__ gates,
                                            float* __restrict__ pg, int tid) {
    constexpr int KKH = KP / 4;
    static_assert(KKH % 4 == 0, "KKH must be multiple of 4");
    const int half = tid >> 8;
    const int lt = tid & 255;
    const int n0 = lt * 2;
    const int kk0 = half * KKH;
    u64 acc0[8], acc1[8];
#pragma unroll
    for (int g = 0; g < 8; g++) { acc0[g] = 0ull; acc1[g] = 0ull; }
    const u64* wp = (const u64*)(W2 + (size_t)kk0 * NG) + lt;
    const float* ipb = ipT + 2 * kk0;
#pragma unroll 1
    for (int b = 0; b < KKH; b += 4) {
        u64 w4[4];
#pragma unroll
        for (int i = 0; i < 4; i++) w4[i] = wp[(size_t)(b + i) * (NG / 2)];
        u64 wn0[4], wn1[4];
#pragma unroll
        for (int i = 0; i < 4; i++) {
            wn0[i] = bf2f2((unsigned)w4[i]);
            wn1[i] = bf2f2((unsigned)(w4[i] >> 32));
        }
        const float* ipk = ipb + 2 * b;
#pragma unroll
        for (int g = 0; g < 8; g++) {
            const float* r = ipk + g * KP;
            ulonglong2 pA = *(const ulonglong2*)(r);
            ulonglong2 pB = *(const ulonglong2*)(r + 4);
            acc0[g] = fma2(wn0[0], pA.x, acc0[g]);
            acc0[g] = fma2(wn0[1], pA.y, acc0[g]);
            acc0[g] = fma2(wn0[2], pB.x, acc0[g]);
            acc0[g] = fma2(wn0[3], pB.y, acc0[g]);
            acc1[g] = fma2(wn1[0], pA.x, acc1[g]);
            acc1[g] = fma2(wn1[1], pA.y, acc1[g]);
            acc1[g] = fma2(wn1[2], pB.x, acc1[g]);
            acc1[g] = fma2(wn1[3], pB.y, acc1[g]);
        }
    }
    if (half) {
        float* pp = pg + n0 * 9;
        float* pq = pg + (n0 + 1) * 9;
#pragma unroll
        for (int g = 0; g < 8; g++) {
            float2 r0 = unpack2(acc0[g]);
            float2 r1 = unpack2(acc1[g]);
            pp[g] = r0.x + r0.y;
            pq[g] = r1.x + r1.y;
        }
    }
    __syncthreads();
    if (!half) {
        const float* pp = pg + n0 * 9;
        const float* pq = pg + (n0 + 1) * 9;
        float b0 = bias[n0], b1 = bias[n0 + 1];
#pragma unroll
        for (int g = 0; g < 8; g++) {
            float2 r0 = unpack2(acc0[g]);
            float2 r1 = unpack2(acc1[g]);
            gates[g * NG + n0]     = r0.x + r0.y + pp[g] + b0;
            gates[g * NG + n0 + 1] = r1.x + r1.y + pq[g] + b1;
        }
    }
}

// ---- gate GEMM (4-g version, stages): same structure, half the g ----
template <int KP>
__device__ __forceinline__ void gates_gemm5g4(const unsigned* __restrict__ W2,
                                              const float* __restrict__ bias,
                                              const float* __restrict__ ipT,  // [4][KP]
                                              float* __restrict__ gates,      // [4][NG]
                                              float* __restrict__ pg,         // [NG][5]
                                              int tid) {
    constexpr int KKH = KP / 4;
    static_assert(KKH % 4 == 0, "KKH must be multiple of 4");
    const int half = tid >> 8;
    const int lt = tid & 255;
    const int n0 = lt * 2;
    const int kk0 = half * KKH;
    u64 acc0[4], acc1[4];
#pragma unroll
    for (int g = 0; g < 4; g++) { acc0[g] = 0ull; acc1[g] = 0ull; }
    const u64* wp = (const u64*)(W2 + (size_t)kk0 * NG) + lt;
#pragma unroll 1
    for (int b = 0; b < KKH; b += 4) {
        u64 w4[4];
#pragma unroll
        for (int i = 0; i < 4; i++) w4[i] = wp[(size_t)(b + i) * (NG / 2)];
        u64 wn0[4], wn1[4];
#pragma unroll
        for (int i = 0; i < 4; i++) {
            wn0[i] = bf2f2((unsigned)w4[i]);
            wn1[i] = bf2f2((unsigned)(w4[i] >> 32));
        }
#pragma unroll
        for (int g = 0; g < 4; g++) {
            const float* r = ipT + g * KP + 2 * (kk0 + b);
            ulonglong2 pA = *(const ulonglong2*)(r);
            ulonglong2 pB = *(const ulonglong2*)(r + 4);
            acc0[g] = fma2(wn0[0], pA.x, acc0[g]);
            acc0[g] = fma2(wn0[1], pA.y, acc0[g]);
            acc0[g] = fma2(wn0[2], pB.x, acc0[g]);
            acc0[g] = fma2(wn0[3], pB.y, acc0[g]);
            acc1[g] = fma2(wn1[0], pA.x, acc1[g]);
            acc1[g] = fma2(wn1[1], pA.y, acc1[g]);
            acc1[g] = fma2(wn1[2], pB.x, acc1[g]);
            acc1[g] = fma2(wn1[3], pB.y, acc1[g]);
        }
    }
    if (half) {
        float* pp = pg + n0 * 5;
        float* pq = pg + (n0 + 1) * 5;
#pragma unroll
        for (int g = 0; g < 4; g++) {
            float2 r0 = unpack2(acc0[g]);
            float2 r1 = unpack2(acc1[g]);
            pp[g] = r0.x + r0.y;
            pq[g] = r1.x + r1.y;
        }
    }
    __syncthreads();
    if (!half) {
        const float* pp = pg + n0 * 5;
        const float* pq = pg + (n0 + 1) * 5;
        float b0 = bias[n0], b1 = bias[n0 + 1];
#pragma unroll
        for (int g = 0; g < 4; g++) {
            float2 r0 = unpack2(acc0[g]);
            float2 r1 = unpack2(acc1[g]);
            gates[g * NG + n0]     = r0.x + r0.y + pp[g] + b0;
            gates[g * NG + n0 + 1] = r1.x + r1.y + pq[g] + b1;
        }
    }
}

// ---------------- setup ----------------
__global__ void setup_kernel(
    const float* __restrict__ e1_Wih, const float* __restrict__ e1_Whh,
    const float* __restrict__ e2_Wih, const float* __restrict__ e2_Whh,
    const float* __restrict__ d_Wih,  const float* __restrict__ d_Whh,
    const float* __restrict__ We1,    const float* __restrict__ We2,
    const float* __restrict__ Wd,     const float* __restrict__ Ud,
    const float* __restrict__ e1_bih, const float* __restrict__ e1_bhh,
    const float* __restrict__ e2_bih, const float* __restrict__ e2_bhh,
    const float* __restrict__ d_bih,  const float* __restrict__ d_bhh) {
    int tid = blockIdx.x * blockDim.x + threadIdx.x;
    int nt = gridDim.x * blockDim.x;
    for (int i = tid; i < (KP1 / 2) * NG; i += nt) {
        int kk = i / NG, n = i % NG;
        int k0 = 2 * kk, k1 = 2 * kk + 1;
        float v0 = 0.f, v1 = 0.f;
        if (k0 < K1) v0 = (k0 < NF1) ? e1_Wih[n * NF1 + k0] : e1_Whh[n * HD + (k0 - NF1)];
        if (k1 < K1) v1 = (k1 < NF1) ? e1_Wih[n * NF1 + k1] : e1_Whh[n * HD + (k1 - NF1)];
        g_W21[i] = (unsigned)__bfloat16_as_ushort(__float2bfloat16(v0))
                 | ((unsigned)__bfloat16_as_ushort(__float2bfloat16(v1)) << 16);
    }
    for (int i = tid; i < (KP2 / 2) * NG; i += nt) {
        int kk = i / NG, n = i % NG;
        int k0 = 2 * kk, k1 = 2 * kk + 1;
        float v0 = 0.f, v1 = 0.f;
        if (k0 < K2) v0 = (k0 < NF2) ? e2_Wih[n * NF2 + k0] : e2_Whh[n * HD + (k0 - NF2)];
        if (k1 < K2) v1 = (k1 < NF2) ? e2_Wih[n * NF2 + k1] : e2_Whh[n * HD + (k1 - NF2)];
        g_W22[i] = (unsigned)__bfloat16_as_ushort(__float2bfloat16(v0))
                 | ((unsigned)__bfloat16_as_ushort(__float2bfloat16(v1)) << 16);
    }
    for (int i = tid; i < (KPD / 2) * NG; i += nt) {
        int kk = i / NG, n = i % NG;
        int k0 = 2 * kk, k1 = 2 * kk + 1;
        float v0 = (k0 < HD) ? d_Wih[n * HD + k0] : d_Whh[n * HD + (k0 - HD)];
        float v1 = (k1 < HD) ? d_Wih[n * HD + k1] : d_Whh[n * HD + (k1 - HD)];
        g_W2d[i] = (unsigned)__bfloat16_as_ushort(__float2bfloat16(v0))
                 | ((unsigned)__bfloat16_as_ushort(__float2bfloat16(v1)) << 16);
    }
    for (int i = tid; i < 256 * TENC; i += nt) {
        int k = i / TENC, ss = i % TENC;
        g_Wet1[i] = We1[ss * 256 + k];
        g_Wet2[i] = We2[ss * 256 + k];
    }
    for (int i = tid; i < 256 * HD; i += nt) {
        int k = i / HD, j = i % HD;
        g_Wdt[i] = Wd[j * 256 + k];
    }
    for (int i = tid; i < HD * HD; i += nt) {
        int k = i / HD, j = i % HD;
        g_Udt[i] = Ud[j * HD + k];
    }
    for (int i = tid; i < NG; i += nt) {
        g_b1[i] = e1_bih[i] + e1_bhh[i];
        g_b2[i] = e2_bih[i] + e2_bhh[i];
        g_bd[i] = d_bih[i] + d_bhh[i];
    }
}

// ---------------- pre1: writes TRANSPOSED [b][f][s] ----------------
__global__ __launch_bounds__(256) void pre1_kernel(
    const float* __restrict__ inp, const float* __restrict__ lab,
    const float* __restrict__ Ue1, const float* __restrict__ Ue1b) {
    __shared__ float xs[TENC * NF1];
    __shared__ float ue[TENC * TENC];
    int b = blockIdx.x, tid = threadIdx.x;
    for (int i = tid; i < TENC * NF1; i += 256) {
        int t = i / NF1, f = i % NF1;
        xs[i] = inp[((size_t)b * TENC + t) * 18 + f + 1];
    }
    for (int i = tid; i < TENC * TENC; i += 256) ue[i] = Ue1[i];
    for (int i = tid; i < TENC; i += 256)
        g_mid[((size_t)b * TENC + i) * NF2 + HD] = lab[(size_t)b * TENC + i];
    __syncthreads();
    for (int i = tid; i < TENC * NF1; i += 256) {
        int ss = i / NF1, f = i % NF1;
        float a = 0.f;
#pragma unroll 8
        for (int t = 0; t < TENC; t++) a += xs[t * NF1 + f] * ue[ss * TENC + t];
        g_pre1[((size_t)b * NF1 + f) * TENC + ss] = a + Ue1b[ss];
    }
}

// ---------------- pre2: writes TRANSPOSED [b][f][s] bf16 ----------------
__global__ __launch_bounds__(256) void pre2_kernel(
    const float* __restrict__ Ue2, const float* __restrict__ Ue2b) {
    __shared__ float ms[TENC * 130];
    __shared__ float ue[TENC * TENC];
    int b = blockIdx.x, tid = threadIdx.x;
    for (int i = tid; i < TENC * NF2; i += 256) {
        int t = i / NF2, f = i % NF2;
        ms[t * 130 + f] = g_mid[(size_t)b * TENC * NF2 + i];
    }
    for (int i = tid; i < TENC; i += 256) ms[i * 130 + 129] = 0.f;
    for (int i = tid; i < TENC * TENC; i += 256) ue[i] = Ue2[i];
    __syncthreads();
    for (int u = tid; u < TENC * 65; u += 256) {
        int ss = u / 65, q = u % 65;
        int f0 = 2 * q;
        u64 acc = 0ull;
#pragma unroll 8
        for (int t = 0; t < TENC; t++)
            acc = fma2(dup2(ue[ss * TENC + t]), *(const u64*)(ms + t * 130 + f0), acc);
        float2 r = unpack2(acc);
        float bb = Ue2b[ss];
        size_t base = (size_t)b * NF2 * TENC;
        g_pre2h[base + (size_t)f0 * TENC + ss] = __float2bfloat16(r.x + bb);
        if (f0 < 128)
            g_pre2h[base + (size_t)(f0 + 1) * TENC + ss] = __float2bfloat16(r.y + bb);
    }
}

// ---------------- ud (bf16 out, transposed) ----------------
__global__ __launch_bounds__(256) void ud_kernel(const float* __restrict__ Udb) {
    extern __shared__ float sm_ud[];
    float* udt = sm_ud;
    float* fs  = sm_ud + 16384;
    int b = blockIdx.x, tid = threadIdx.x;
    for (int i = tid; i < HD * HD; i += 256) udt[i] = g_Udt[i];
    for (int i = tid; i < TENC * HD; i += 256) {
        int t = i >> 7, k = i & 127;
        fs[t * 129 + k] = g_fin[(size_t)b * TENC * HD + i];
    }
    __syncthreads();
    for (int u = tid; u < 32 * TENC; u += 256) {
        int t = u % TENC, jq = u / TENC;
        int j0 = 4 * jq;
        float a0 = Udb[j0], a1 = Udb[j0 + 1], a2 = Udb[j0 + 2], a3 = Udb[j0 + 3];
#pragma unroll 8
        for (int k = 0; k < HD; k++) {
            float f = fs[t * 129 + k];
            float4 uu = *(const float4*)(udt + k * HD + j0);
            a0 += f * uu.x; a1 += f * uu.y; a2 += f * uu.z; a3 += f * uu.w;
        }
        size_t base = (size_t)b * HD * TENC;
        g_udTh[base + (size_t)(j0 + 0) * TENC + t] = __float2bfloat16(a0);
        g_udTh[base + (size_t)(j0 + 1) * TENC + t] = __float2bfloat16(a1);
        g_udTh[base + (size_t)(j0 + 2) * TENC + t] = __float2bfloat16(a2);
        g_udTh[base + (size_t)(j0 + 3) * TENC + t] = __float2bfloat16(a3);
    }
}

// ---------------- encoder stage: G=4, 2 CTAs/SM, pre from global ----------------
template <int K, int KP, int NF, bool PB16>
__global__ __launch_bounds__(NTH, 2) void stage_kernel(
    const float* __restrict__ inp,
    const float* __restrict__ Ve, const float* __restrict__ Veb,
    const unsigned* __restrict__ W2, const float* __restrict__ bsum,
    const float* __restrict__ Wet, const float* __restrict__ preF,
    float* __restrict__ outb, int ostride) {
    extern __shared__ float sm[];
    constexpr int O_WET = 0;                         // 12288 (fp32 [k][48])
    constexpr int O_HCT = 12288;                     // 256*HS_STR = 1536
    constexpr int O_WE  = O_HCT + 1536;              // 4*48 = 192
    constexpr int O_WEP = O_WE + 192;                // 192
    constexpr int O_SC  = O_WEP + 192;               // 4*132 = 528
    constexpr int O_AL  = O_SC + 528;                // 528
    constexpr int O_IP  = O_AL + 528;                // 4*KP
    constexpr int O_GT  = O_IP + 4 * KP;             // 2048
    constexpr int O_PG  = O_GT + 2048;               // 512*5 = 2560
    constexpr int O_BS  = O_PG + 2560;               // 512
    constexpr int O_VV  = O_BS + 512;                // 136

    float* wet  = sm + O_WET;
    float* hcT  = sm + O_HCT;
    float* ipT  = sm + O_IP;
    float* gates = sm + O_GT;
    float* pg   = sm + O_PG;
    float* bias = sm + O_BS;
    float* vvec = sm + O_VV;

    const int tid = threadIdx.x, bid = blockIdx.x;
    const int p = tid >> 7;          // group = batch element 0..3
    const int lt = tid & 127;
    const int gw = lt >> 5;
    const int lane = tid & 31;
    const int b = bid * GS + p;

    float* weg  = sm + O_WE  + p * 48;
    float* wepg = sm + O_WEP + p * 48;
    float* scg  = sm + O_SC  + p * 132;
    float* alg  = sm + O_AL  + p * 132;

    for (int i = tid; i < 256 * TENC; i += NTH) wet[i] = Wet[i];
    for (int i = tid; i < 256 * HS_STR; i += NTH) hcT[i] = 0.f;
    for (int i = tid; i < NG; i += NTH) bias[i] = bsum[i];
    for (int i = tid; i < TENC; i += NTH) vvec[i] = Ve[i];
    if (tid == 0) vvec[130] = Veb[0];
    for (int i = tid; i < 4 * KP; i += NTH) ipT[i] = 0.f;
    __syncthreads();

    // A-phase mapping: 48 threads/group = 2 khalves x 24 ss-pairs
    const int akh = (lt < 48) ? (lt / 24) : 0;
    const int asp = (lt < 48) ? (lt % 24) : 0;

    for (int t = 0; t < TENC; t++) {
        // x prefetch for D (registers, read during A/B latency)
        float xr0 = 0.f, xr1 = 0.f, xr2 = 0.f, xr3 = 0.f, xr4 = 0.f;
        if (gw == 0) {
            if (PB16) {
                const float* xp = g_mid + ((size_t)b * TENC + t) * NF2;
                xr0 = xp[lane]; xr1 = xp[lane + 32];
                xr2 = xp[lane + 64]; xr3 = xp[lane + 96];
                if (lane == 0) xr4 = xp[128];
            } else {
                if (lane < NF)
                    xr0 = inp[((size_t)b * TENC + t) * 18 + lane + 1];
            }
        }
        // A: we projection for this group's element (48 threads, 2-way k-split)
        if (lt < 48) {
            int kb = akh * 128;
            int ss0 = 2 * asp;
            u64 acc = 0ull;
#pragma unroll 8
            for (int kk = 0; kk < 128; kk++) {
                int k = kb + kk;
                u64 wv = *(const u64*)(wet + k * TENC + ss0);
                acc = fma2(wv, dup2(hcT[k * HS_STR + p]), acc);
            }
            float2 v = unpack2(acc);
            float* dst = akh ? wepg : weg;
            dst[ss0] = v.x;
            dst[ss0 + 1] = v.y;
        }
        barg(p);
        if (lt < 48) weg[lt] += wepg[lt];
        barg(p);
        // B: scores from GLOBAL transposed pre (coalesced per-thread rows)
        {
            float bb = vvec[130];
            for (int f = lt; f < NF; f += 128) {
                float a = 0.f;
                if (PB16) {
                    const __nv_bfloat16* pp =
                        g_pre2h + ((size_t)b * NF + f) * TENC;
#pragma unroll 8
                    for (int ss = 0; ss < TENC; ss++)
                        a += tanha(weg[ss] + __bfloat162float(pp[ss])) * vvec[ss];
                } else {
                    const float* pp = preF + ((size_t)b * NF + f) * TENC;
#pragma unroll 8
                    for (int ss = 0; ss < TENC; ss++)
                        a += tanha(weg[ss] + pp[ss]) * vvec[ss];
                }
                scg[f] = a + bb;
            }
        }
        barg(p);
        // softmax + D fused (warp 0 of group)
        if (gw == 0) {
            warp_softmax(scg, alg, NF, lane);
            __syncwarp();
            if (PB16) {
                ipT[p * KP + lane]      = xr0 * alg[lane];
                ipT[p * KP + lane + 32] = xr1 * alg[lane + 32];
                ipT[p * KP + lane + 64] = xr2 * alg[lane + 64];
                ipT[p * KP + lane + 96] = xr3 * alg[lane + 96];
                if (lane == 0) ipT[p * KP + 128] = xr4 * alg[128];
            } else {
                if (lane < NF) ipT[p * KP + lane] = xr0 * alg[lane];
            }
        }
        __syncthreads();
        gates_gemm5g4<KP>(W2, bias, ipT, gates, pg, tid);
        __syncthreads();
        // F: cell update (512 items = 1/thread) + output + next-step ipT h rows
        {
            int g = tid >> 7, j = tid & 127;
            float gi = gates[g * NG + j];
            float gf = gates[g * NG + HD + j];
            float gg = gates[g * NG + 2 * HD + j];
            float go = gates[g * NG + 3 * HD + j];
            float c  = hcT[(128 + j) * HS_STR + g];
            float c2 = siga(gf) * c + siga(gi) * tanha(gg);
            float h  = siga(go) * tanha(c2);
            hcT[j * HS_STR + g] = h;
            hcT[(128 + j) * HS_STR + g] = c2;
            ipT[g * KP + NF + j] = h;
            outb[((size_t)(bid * GS + g) * TENC + t) * ostride + j] = h;
        }
        __syncthreads();
    }
}

// ---------------- decoder (unchanged, G=8) ----------------
#define D_O_WDT 0
#define D_O_HCT 32768
#define D_O_WD  35328
#define D_O_SC  36352
#define D_O_AL  36736
#define D_O_IP  37120
#define D_O_GT  39168
#define D_O_PG  43264
#define D_O_BS  47872
#define D_O_VV  48384
#define D_O_VR  48520
#define DEC_SMEM_FL 48656

__global__ __launch_bounds__(NTH, 1) void decoder_kernel(
    const float* __restrict__ Vd, const float* __restrict__ Vdb,
    const float* __restrict__ regW, const float* __restrict__ regb,
    float* __restrict__ out) {
    extern __shared__ float sm[];
    float* wdt  = sm + D_O_WDT;
    float* hcT  = sm + D_O_HCT;
    float* wd   = sm + D_O_WD;
    float* score = sm + D_O_SC;
    float* alpha = sm + D_O_AL;
    float* ipT  = sm + D_O_IP;     // [G][KPD]
    float* gates = sm + D_O_GT;
    float* pg   = sm + D_O_PG;
    float* bias = sm + D_O_BS;
    float* vvec = sm + D_O_VV;
    float* vreg = sm + D_O_VR;
    float* part = gates;

    const int tid = threadIdx.x, bid = blockIdx.x;
    const int wid = tid >> 5, lane = tid & 31;

    for (int i = tid; i < 256 * HD; i += NTH) wdt[i] = g_Wdt[i];
    for (int i = tid; i < 256 * HCT_STR; i += NTH) hcT[i] = 0.f;
    for (int i = tid; i < NG; i += NTH) bias[i] = g_bd[i];
    for (int i = tid; i < KPD * G; i += NTH) ipT[i] = 0.f;
    for (int i = tid; i < HD; i += NTH) { vvec[i] = Vd[i]; vreg[i] = regW[i]; }
    if (tid == 0) { vvec[130] = Vdb[0]; vreg[130] = regb[0]; }
    __syncthreads();

    bool sval = tid < G * TENC;
    int sg = sval ? tid / TENC : 0, stt = sval ? tid % TENC : 0;
    const __nv_bfloat16* up = g_udTh + ((size_t)(bid * G + sg) * HD) * TENC + stt;
    int dg = tid >> 6, dj = (tid & 63) * 2;
    const float* fp = g_fin + ((size_t)(bid * G + dg) * TENC) * HD + dj;
    const int s8 = tid >> 6;
    const int jp = tid & 63, j0 = 2 * jp;

    for (int sd = 0; sd < DSTEPS; sd++) {
        {
            u64 a0 = 0, a1 = 0, a2 = 0, a3 = 0, a4 = 0, a5 = 0, a6 = 0, a7 = 0;
            int kb = s8 * 32;
#pragma unroll 8
            for (int kk = 0; kk < 32; kk++) {
                int k = kb + kk;
                float2 w = *(const float2*)(wdt + k * HD + j0);
                u64 w0 = dup2(w.x), w1 = dup2(w.y);
                const float* hp = hcT + k * HCT_STR;
                u64 h01 = *(const u64*)(hp);
                u64 h23 = *(const u64*)(hp + 2);
                u64 h45 = *(const u64*)(hp + 4);
                u64 h67 = *(const u64*)(hp + 6);
                a0 = fma2(w0, h01, a0); a1 = fma2(w0, h23, a1);
                a2 = fma2(w0, h45, a2); a3 = fma2(w0, h67, a3);
                a4 = fma2(w1, h01, a4); a5 = fma2(w1, h23, a5);
                a6 = fma2(w1, h45, a6); a7 = fma2(w1, h67, a7);
            }
            float* pp = part + s8 * 1024 + j0 * 8;
            float2 r;
            r = unpack2(a0); pp[0] = r.x; pp[1] = r.y;
            r = unpack2(a1); pp[2] = r.x; pp[3] = r.y;
            r = unpack2(a2); pp[4] = r.x; pp[5] = r.y;
            r = unpack2(a3); pp[6] = r.x; pp[7] = r.y;
            pp += 8;
            r = unpack2(a4); pp[0] = r.x; pp[1] = r.y;
            r = unpack2(a5); pp[2] = r.x; pp[3] = r.y;
            r = unpack2(a6); pp[4] = r.x; pp[5] = r.y;
            r = unpack2(a7); pp[6] = r.x; pp[7] = r.y;
        }
        __syncthreads();
#pragma unroll
        for (int u = 0; u < 2; u++) {
            int o = tid + u * NTH;
            float s = 0.f;
#pragma unroll
            for (int q = 0; q < 8; q++) s += part[q * 1024 + o];
            int j = o >> 3, g = o & 7;
            wd[g * HD + j] = s;
        }
        __syncthreads();
        {
            float a = 0.f;
#pragma unroll 4
            for (int j = 0; j < HD; j++)
                a += tanha(wd[sg * HD + j] + __bfloat162float(up[(size_t)j * TENC])) * vvec[j];
            if (sval) score[sg * TENC + stt] = a + vvec[130];
        }
        __syncthreads();
        if (wid < G) warp_softmax(score + wid * TENC, alpha + wid * TENC, TENC, lane);
        __syncthreads();
        {
            float a0 = 0.f, a1 = 0.f;
#pragma unroll 4
            for (int tt = 0; tt < TENC; tt++) {
                float al = alpha[dg * TENC + tt];
                float2 f2 = *(const float2*)(fp + (size_t)tt * HD);
                a0 += al * f2.x; a1 += al * f2.y;
            }
            ipT[dg * KPD + dj] = a0;
            ipT[dg * KPD + dj + 1] = a1;
        }
        __syncthreads();
        gates_gemm5<KPD>(g_W2d, bias, ipT, gates, pg, tid);
        __syncthreads();
        for (int idx = tid; idx < G * HD; idx += NTH) {
            int g = idx >> 7, j = idx & 127;
            float gi = gates[g * NG + j];
            float gf = gates[g * NG + HD + j];
            float gg = gates[g * NG + 2 * HD + j];
            float go = gates[g * NG + 3 * HD + j];
            float c  = hcT[(128 + j) * HCT_STR + g];
            float c2 = siga(gf) * c + siga(gi) * tanha(gg);
            float h  = siga(go) * tanha(c2);
            hcT[j * HCT_STR + g] = h;
            hcT[(128 + j) * HCT_STR + g] = c2;
            ipT[g * KPD + HD + j] = h;
        }
        __syncthreads();
        if (sd >= DSTEPS - TDEC && wid < G) {
            float a = 0.f;
#pragma unroll
            for (int r = 0; r < 4; r++)
                a += hcT[(lane + 32 * r) * HCT_STR + wid] * vreg[lane + 32 * r];
#pragma unroll
            for (int o = 16; o; o >>= 1) a += __shfl_xor_sync(0xffffffffu, a, o);
            if (lane == 0)
                out[(size_t)(bid * G + wid) * TDEC + (sd - (DSTEPS - TDEC))] = a + vreg[130];
        }
    }
}

// ---------------- launch ----------------
extern "C" void kernel_launch(void* const* d_in, const int* in_sizes, int n_in,
                              void* d_out, int out_size) {
    const float* input_p_q = (const float*)d_in[0];
    const float* label_p   = (const float*)d_in[1];
    const float* Ue1_W = (const float*)d_in[2];
    const float* Ue1_b = (const float*)d_in[3];
    const float* We1_W = (const float*)d_in[4];
    const float* Ve1_W = (const float*)d_in[5];
    const float* Ve1_b = (const float*)d_in[6];
    const float* Ue2_W = (const float*)d_in[7];
    const float* Ue2_b = (const float*)d_in[8];
    const float* We2_W = (const float*)d_in[9];
    const float* Ve2_W = (const float*)d_in[10];
    const float* Ve2_b = (const float*)d_in[11];
    const float* Ud_W  = (const float*)d_in[12];
    const float* Ud_b  = (const float*)d_in[13];
    const float* Wd_W  = (const float*)d_in[14];
    const float* Vd_W  = (const float*)d_in[15];
    const float* Vd_b  = (const float*)d_in[16];
    const float* e1_Wih = (const float*)d_in[17];
    const float* e1_Whh = (const float*)d_in[18];
    const float* e1_bih = (const float*)d_in[19];
    const float* e1_bhh = (const float*)d_in[20];
    const float* e2_Wih = (const float*)d_in[21];
    const float* e2_Whh = (const float*)d_in[22];
    const float* e2_bih = (const float*)d_in[23];
    const float* e2_bhh = (const float*)d_in[24];
    const float* d_Wih  = (const float*)d_in[25];
    const float* d_Whh  = (const float*)d_in[26];
    const float* d_bih  = (const float*)d_in[27];
    const float* d_bhh  = (const float*)d_in[28];
    const float* reg_W  = (const float*)d_in[29];
    const float* reg_b  = (const float*)d_in[30];
    float* out = (float*)d_out;

    unsigned *p_W21, *p_W22;
    float *p_Wet1, *p_Wet2;
    float *p_b1, *p_b2, *p_pre1, *p_mid, *p_fin;
    cudaGetSymbolAddress((void**)&p_W21, g_W21);
    cudaGetSymbolAddress((void**)&p_W22, g_W22);
    cudaGetSymbolAddress((void**)&p_Wet1, g_Wet1);
    cudaGetSymbolAddress((void**)&p_Wet2, g_Wet2);
    cudaGetSymbolAddress((void**)&p_b1, g_b1);
    cudaGetSymbolAddress((void**)&p_b2, g_b2);
    cudaGetSymbolAddress((void**)&p_pre1, g_pre1);
    cudaGetSymbolAddress((void**)&p_mid, g_mid);
    cudaGetSymbolAddress((void**)&p_fin, g_fin);

    const int S1_FL = 12288 + 1536 + 192 + 192 + 528 + 528 + 4 * KP1
                      + 2048 + 2560 + 512 + 136;
    const int S2_FL = 12288 + 1536 + 192 + 192 + 528 + 528 + 4 * KP2
                      + 2048 + 2560 + 512 + 136;
    const int STAGE1_SMEM = S1_FL * 4;
    const int STAGE2_SMEM = S2_FL * 4;
    const int DEC_SMEM    = DEC_SMEM_FL * 4;
    const int UD_SMEM     = (16384 + TENC * 129) * 4;

    cudaFuncSetAttribute((const void*)stage_kernel<K1, KP1, NF1, false>,
                         cudaFuncAttributeMaxDynamicSharedMemorySize, STAGE1_SMEM);
    cudaFuncSetAttribute((const void*)stage_kernel<K2, KP2, NF2, true>,
                         cudaFuncAttributeMaxDynamicSharedMemorySize, STAGE2_SMEM);
    cudaFuncSetAttribute((const void*)decoder_kernel,
                         cudaFuncAttributeMaxDynamicSharedMemorySize, DEC_SMEM);
    cudaFuncSetAttribute((const void*)ud_kernel,
                         cudaFuncAttributeMaxDynamicSharedMemorySize, UD_SMEM);

    nop_kernel<<<1, 32>>>();   // keeps ncu capture slot on stage1
    setup_kernel<<<128, 256>>>(e1_Wih, e1_Whh, e2_Wih, e2_Whh, d_Wih, d_Whh,
                               We1_W, We2_W, Wd_W, Ud_W,
                               e1_bih, e1_bhh, e2_bih, e2_bhh, d_bih, d_bhh);
    pre1_kernel<<<BTOT, 256>>>(input_p_q, label_p, Ue1_W, Ue1_b);
    stage_kernel<K1, KP1, NF1, false><<<NCTA_S, NTH, STAGE1_SMEM>>>(
        input_p_q, Ve1_W, Ve1_b, p_W21, p_b1, p_Wet1, p_pre1, p_mid, NF2);
    pre2_kernel<<<BTOT, 256>>>(Ue2_W, Ue2_b);
    stage_kernel<K2, KP2, NF2, true><<<NCTA_S, NTH, STAGE2_SMEM>>>(
        input_p_q, Ve2_W, Ve2_b, p_W22, p_b2, p_Wet2, nullptr, p_fin, HD);
    ud_kernel<<<BTOT, 256, UD_SMEM>>>(Ud_b);
    decoder_kernel<<<NCTA, NTH, DEC_SMEM>>>(Vd_W, Vd_b, reg_W, reg_b, out);
}

// round 14
// speedup vs baseline: 1.1469x; 1.1469x over previous
#include <cuda_runtime.h>
#include <cuda_bf16.h>

#define TENC 48
#define TDEC 24
#define DSTEPS 30
#define HD 128
#define NF1 17
#define NF2 129
#define K1 145
#define KP1 160
#define K2 257
#define KP2 272
#define KD 256
#define KPD 256
#define G 8
#define NCTA 128
#define NTH 512
#define NTHS 1024
#define NG 512
#define BTOT 1024
#define HCT_STR 10

typedef unsigned long long u64;

// ---------------- device scratch (allocation-free) ----------------
__device__ unsigned g_W21[(KP1 / 2) * NG];   // [k/2][n], u32 = bf16(w[2k][n]) | bf16(w[2k+1][n])<<16
__device__ unsigned g_W22[(KP2 / 2) * NG];
__device__ unsigned g_W2d[(KPD / 2) * NG];
__device__ float g_Wet1[256 * TENC];
__device__ float g_Wet2[256 * TENC];
__device__ float g_Wdt[256 * HD];             // [k][j]
__device__ float g_Udt[HD * HD];
__device__ float g_b1[NG], g_b2[NG], g_bd[NG];
__device__ float g_pre1[BTOT * TENC * NF1];           // [b][t=s][f] fp32
__device__ __nv_bfloat16 g_pre2h[BTOT * TENC * NF2];  // [b][s][f] bf16
__device__ float g_mid[BTOT * TENC * NF2];            // [b][t][f] (f=128 label)
__device__ float g_fin[BTOT * TENC * HD];             // [b][t][j]
__device__ __nv_bfloat16 g_udTh[BTOT * HD * TENC];    // [b][j][t] bf16

// ---------------- math helpers ----------------
__device__ __forceinline__ float tanha(float x) {
    float y; asm("tanh.approx.f32 %0, %1;" : "=f"(y) : "f"(x)); return y;
}
__device__ __forceinline__ float siga(float x) {
    return fmaf(tanha(0.5f * x), 0.5f, 0.5f);
}
__device__ __forceinline__ u64 fma2(u64 a, u64 b, u64 c) {
    u64 d; asm("fma.rn.f32x2 %0, %1, %2, %3;" : "=l"(d) : "l"(a), "l"(b), "l"(c)); return d;
}
__device__ __forceinline__ u64 dup2(float x) {
    u64 d; unsigned r = __float_as_uint(x);
    asm("mov.b64 %0, {%1, %1};" : "=l"(d) : "r"(r)); return d;
}
__device__ __forceinline__ float2 unpack2(u64 a) {
    unsigned l, h;
    asm("mov.b64 {%0, %1}, %2;" : "=r"(l), "=r"(h) : "l"(a));
    return make_float2(__uint_as_float(l), __uint_as_float(h));
}
__device__ __forceinline__ u64 dup2bits(unsigned bits) {
    u64 d; asm("mov.b64 %0, {%1, %1};" : "=l"(d) : "r"(bits)); return d;
}
// bf16-pair -> packed f32x2
__device__ __forceinline__ u64 bf2f2(unsigned w) {
    unsigned lo = w << 16;
    unsigned hi = w & 0xffff0000u;
    u64 d;
    asm("mov.b64 %0, {%1, %2};" : "=l"(d) : "r"(lo), "r"(hi));
    return d;
}
__device__ __forceinline__ void barg(int p) {
    asm volatile("bar.sync %0, %1;" :: "r"(p + 1), "r"(128) : "memory");
}

__device__ __forceinline__ void warp_softmax(const float* score_row, float* alpha_row,
                                             int F, int lane) {
    float mx = -1e30f;
    for (int f = lane; f < F; f += 32) mx = fmaxf(mx, score_row[f]);
#pragma unroll
    for (int o = 16; o; o >>= 1) mx = fmaxf(mx, __shfl_xor_sync(0xffffffffu, mx, o));
    float sm = 0.f;
    for (int f = lane; f < F; f += 32) {
        float e = __expf(score_row[f] - mx);
        alpha_row[f] = e;
        sm += e;
    }
#pragma unroll
    for (int o = 16; o; o >>= 1) sm += __shfl_xor_sync(0xffffffffu, sm, o);
    float inv = __fdividef(1.f, sm);
    for (int f = lane; f < F; f += 32) alpha_row[f] *= inv;
}

__global__ void nop_kernel() {}

// ---- stage gate GEMM (1024 threads): 1 col/thread, 2-way K-split, ipK [k][8] ----
template <int KP>
__device__ __forceinline__ void gates_gemmW(const unsigned* __restrict__ W2,
                                            const float* __restrict__ bias,
                                            const float* __restrict__ ipK,  // [KP][8]
                                            float* __restrict__ gates,      // [8][NG]
                                            float* __restrict__ pg,         // [NG][9]
                                            int tid) {
    constexpr int KKH = KP / 4;     // u32-rows per half
    static_assert(KKH % 4 == 0, "KKH must be multiple of 4");
    const int half = tid >> 9;
    const int lt = tid & 511;       // column
    const int kk0 = half * KKH;
    u64 a01 = 0, a23 = 0, a45 = 0, a67 = 0;
    const unsigned* wp = W2 + (size_t)kk0 * NG + lt;
    const float* ipb = ipK + (2 * kk0) * 8;
#pragma unroll 1
    for (int b = 0; b < KKH; b += 4) {
        unsigned w4[4];
#pragma unroll
        for (int i = 0; i < 4; i++) w4[i] = wp[(size_t)(b + i) * NG];
#pragma unroll
        for (int i = 0; i < 4; i++) {
            u64 wk0 = dup2bits(w4[i] << 16);
            u64 wk1 = dup2bits(w4[i] & 0xffff0000u);
            const u64* ip0 = (const u64*)(ipb + (2 * (b + i)) * 8);
            u64 g01 = ip0[0], g23 = ip0[1], g45 = ip0[2], g67 = ip0[3];
            a01 = fma2(wk0, g01, a01); a23 = fma2(wk0, g23, a23);
            a45 = fma2(wk0, g45, a45); a67 = fma2(wk0, g67, a67);
            u64 h01 = ip0[4], h23 = ip0[5], h45 = ip0[6], h67 = ip0[7];
            a01 = fma2(wk1, h01, a01); a23 = fma2(wk1, h23, a23);
            a45 = fma2(wk1, h45, a45); a67 = fma2(wk1, h67, a67);
        }
    }
    if (half) {
        float* pp = pg + lt * 9;
        float2 r;
        r = unpack2(a01); pp[0] = r.x; pp[1] = r.y;
        r = unpack2(a23); pp[2] = r.x; pp[3] = r.y;
        r = unpack2(a45); pp[4] = r.x; pp[5] = r.y;
        r = unpack2(a67); pp[6] = r.x; pp[7] = r.y;
    }
    __syncthreads();
    if (!half) {
        const float* pp = pg + lt * 9;
        float bb = bias[lt];
        float2 r;
        r = unpack2(a01); gates[0 * NG + lt] = r.x + pp[0] + bb;
                          gates[1 * NG + lt] = r.y + pp[1] + bb;
        r = unpack2(a23); gates[2 * NG + lt] = r.x + pp[2] + bb;
                          gates[3 * NG + lt] = r.y + pp[3] + bb;
        r = unpack2(a45); gates[4 * NG + lt] = r.x + pp[4] + bb;
                          gates[5 * NG + lt] = r.y + pp[5] + bb;
        r = unpack2(a67); gates[6 * NG + lt] = r.x + pp[6] + bb;
                          gates[7 * NG + lt] = r.y + pp[7] + bb;
    }
}

// ---- decoder gate GEMM (512 threads, round-12 proven): ipT [g][KP] ----
template <int KP>
__device__ __forceinline__ void gates_gemm5(const unsigned* __restrict__ W2,
                                            const float* __restrict__ bias,
                                            const float* __restrict__ ipT,
                                            float* __restrict__ gates,
                                            float* __restrict__ pg, int tid) {
    constexpr int KKH = KP / 4;
    static_assert(KKH % 4 == 0, "KKH must be multiple of 4");
    const int half = tid >> 8;
    const int lt = tid & 255;
    const int n0 = lt * 2;
    const int kk0 = half * KKH;
    u64 acc0[8], acc1[8];
#pragma unroll
    for (int g = 0; g < 8; g++) { acc0[g] = 0ull; acc1[g] = 0ull; }
    const u64* wp = (const u64*)(W2 + (size_t)kk0 * NG) + lt;
    const float* ipb = ipT + 2 * kk0;
#pragma unroll 1
    for (int b = 0; b < KKH; b += 4) {
        u64 w4[4];
#pragma unroll
        for (int i = 0; i < 4; i++) w4[i] = wp[(size_t)(b + i) * (NG / 2)];
        u64 wn0[4], wn1[4];
#pragma unroll
        for (int i = 0; i < 4; i++) {
            wn0[i] = bf2f2((unsigned)w4[i]);
            wn1[i] = bf2f2((unsigned)(w4[i] >> 32));
        }
        const float* ipk = ipb + 2 * b;
#pragma unroll
        for (int g = 0; g < 8; g++) {
            const float* r = ipk + g * KP;
            ulonglong2 pA = *(const ulonglong2*)(r);
            ulonglong2 pB = *(const ulonglong2*)(r + 4);
            acc0[g] = fma2(wn0[0], pA.x, acc0[g]);
            acc0[g] = fma2(wn0[1], pA.y, acc0[g]);
            acc0[g] = fma2(wn0[2], pB.x, acc0[g]);
            acc0[g] = fma2(wn0[3], pB.y, acc0[g]);
            acc1[g] = fma2(wn1[0], pA.x, acc1[g]);
            acc1[g] = fma2(wn1[1], pA.y, acc1[g]);
            acc1[g] = fma2(wn1[2], pB.x, acc1[g]);
            acc1[g] = fma2(wn1[3], pB.y, acc1[g]);
        }
    }
    if (half) {
        float* pp = pg + n0 * 9;
        float* pq = pg + (n0 + 1) * 9;
#pragma unroll
        for (int g = 0; g < 8; g++) {
            float2 r0 = unpack2(acc0[g]);
            float2 r1 = unpack2(acc1[g]);
            pp[g] = r0.x + r0.y;
            pq[g] = r1.x + r1.y;
        }
    }
    __syncthreads();
    if (!half) {
        const float* pp = pg + n0 * 9;
        const float* pq = pg + (n0 + 1) * 9;
        float b0 = bias[n0], b1 = bias[n0 + 1];
#pragma unroll
        for (int g = 0; g < 8; g++) {
            float2 r0 = unpack2(acc0[g]);
            float2 r1 = unpack2(acc1[g]);
            gates[g * NG + n0]     = r0.x + r0.y + pp[g] + b0;
            gates[g * NG + n0 + 1] = r1.x + r1.y + pq[g] + b1;
        }
    }
}

// ---------------- setup ----------------
__global__ void setup_kernel(
    const float* __restrict__ e1_Wih, const float* __restrict__ e1_Whh,
    const float* __restrict__ e2_Wih, const float* __restrict__ e2_Whh,
    const float* __restrict__ d_Wih,  const float* __restrict__ d_Whh,
    const float* __restrict__ We1,    const float* __restrict__ We2,
    const float* __restrict__ Wd,     const float* __restrict__ Ud,
    const float* __restrict__ e1_bih, const float* __restrict__ e1_bhh,
    const float* __restrict__ e2_bih, const float* __restrict__ e2_bhh,
    const float* __restrict__ d_bih,  const float* __restrict__ d_bhh) {
    int tid = blockIdx.x * blockDim.x + threadIdx.x;
    int nt = gridDim.x * blockDim.x;
    for (int i = tid; i < (KP1 / 2) * NG; i += nt) {
        int kk = i / NG, n = i % NG;
        int k0 = 2 * kk, k1 = 2 * kk + 1;
        float v0 = 0.f, v1 = 0.f;
        if (k0 < K1) v0 = (k0 < NF1) ? e1_Wih[n * NF1 + k0] : e1_Whh[n * HD + (k0 - NF1)];
        if (k1 < K1) v1 = (k1 < NF1) ? e1_Wih[n * NF1 + k1] : e1_Whh[n * HD + (k1 - NF1)];
        g_W21[i] = (unsigned)__bfloat16_as_ushort(__float2bfloat16(v0))
                 | ((unsigned)__bfloat16_as_ushort(__float2bfloat16(v1)) << 16);
    }
    for (int i = tid; i < (KP2 / 2) * NG; i += nt) {
        int kk = i / NG, n = i % NG;
        int k0 = 2 * kk, k1 = 2 * kk + 1;
        float v0 = 0.f, v1 = 0.f;
        if (k0 < K2) v0 = (k0 < NF2) ? e2_Wih[n * NF2 + k0] : e2_Whh[n * HD + (k0 - NF2)];
        if (k1 < K2) v1 = (k1 < NF2) ? e2_Wih[n * NF2 + k1] : e2_Whh[n * HD + (k1 - NF2)];
        g_W22[i] = (unsigned)__bfloat16_as_ushort(__float2bfloat16(v0))
                 | ((unsigned)__bfloat16_as_ushort(__float2bfloat16(v1)) << 16);
    }
    for (int i = tid; i < (KPD / 2) * NG; i += nt) {
        int kk = i / NG, n = i % NG;
        int k0 = 2 * kk, k1 = 2 * kk + 1;
        float v0 = (k0 < HD) ? d_Wih[n * HD + k0] : d_Whh[n * HD + (k0 - HD)];
        float v1 = (k1 < HD) ? d_Wih[n * HD + k1] : d_Whh[n * HD + (k1 - HD)];
        g_W2d[i] = (unsigned)__bfloat16_as_ushort(__float2bfloat16(v0))
                 | ((unsigned)__bfloat16_as_ushort(__float2bfloat16(v1)) << 16);
    }
    for (int i = tid; i < 256 * TENC; i += nt) {
        int k = i / TENC, ss = i % TENC;
        g_Wet1[i] = We1[ss * 256 + k];
        g_Wet2[i] = We2[ss * 256 + k];
    }
    for (int i = tid; i < 256 * HD; i += nt) {
        int k = i / HD, j = i % HD;
        g_Wdt[i] = Wd[j * 256 + k];
    }
    for (int i = tid; i < HD * HD; i += nt) {
        int k = i / HD, j = i % HD;
        g_Udt[i] = Ud[j * HD + k];
    }
    for (int i = tid; i < NG; i += nt) {
        g_b1[i] = e1_bih[i] + e1_bhh[i];
        g_b2[i] = e2_bih[i] + e2_bhh[i];
        g_bd[i] = d_bih[i] + d_bhh[i];
    }
}

// ---------------- pre1 ----------------
__global__ __launch_bounds__(256) void pre1_kernel(
    const float* __restrict__ inp, const float* __restrict__ lab,
    const float* __restrict__ Ue1, const float* __restrict__ Ue1b) {
    __shared__ float xs[TENC * NF1];
    __shared__ float ue[TENC * TENC];
    int b = blockIdx.x, tid = threadIdx.x;
    for (int i = tid; i < TENC * NF1; i += 256) {
        int t = i / NF1, f = i % NF1;
        xs[i] = inp[((size_t)b * TENC + t) * 18 + f + 1];
    }
    for (int i = tid; i < TENC * TENC; i += 256) ue[i] = Ue1[i];
    for (int i = tid; i < TENC; i += 256)
        g_mid[((size_t)b * TENC + i) * NF2 + HD] = lab[(size_t)b * TENC + i];
    __syncthreads();
    for (int i = tid; i < TENC * NF1; i += 256) {
        int ss = i / NF1, f = i % NF1;
        float a = 0.f;
#pragma unroll 8
        for (int t = 0; t < TENC; t++) a += xs[t * NF1 + f] * ue[ss * TENC + t];
        g_pre1[(size_t)b * TENC * NF1 + i] = a + Ue1b[ss];
    }
}

// ---------------- pre2 (bf16 out, [b][s][f]) ----------------
__global__ __launch_bounds__(256) void pre2_kernel(
    const float* __restrict__ Ue2, const float* __restrict__ Ue2b) {
    __shared__ float ms[TENC * 130];
    __shared__ float ue[TENC * TENC];
    int b = blockIdx.x, tid = threadIdx.x;
    for (int i = tid; i < TENC * NF2; i += 256) {
        int t = i / NF2, f = i % NF2;
        ms[t * 130 + f] = g_mid[(size_t)b * TENC * NF2 + i];
    }
    for (int i = tid; i < TENC; i += 256) ms[i * 130 + 129] = 0.f;
    for (int i = tid; i < TENC * TENC; i += 256) ue[i] = Ue2[i];
    __syncthreads();
    for (int u = tid; u < TENC * 65; u += 256) {
        int ss = u / 65, q = u % 65;
        int f0 = 2 * q;
        u64 acc = 0ull;
#pragma unroll 8
        for (int t = 0; t < TENC; t++)
            acc = fma2(dup2(ue[ss * TENC + t]), *(const u64*)(ms + t * 130 + f0), acc);
        float2 r = unpack2(acc);
        float bb = Ue2b[ss];
        size_t base = (size_t)b * TENC * NF2 + ss * NF2;
        g_pre2h[base + f0] = __float2bfloat16(r.x + bb);
        if (f0 < 128) g_pre2h[base + f0 + 1] = __float2bfloat16(r.y + bb);
    }
}

// ---------------- ud (bf16 out, transposed) ----------------
__global__ __launch_bounds__(256) void ud_kernel(const float* __restrict__ Udb) {
    extern __shared__ float sm_ud[];
    float* udt = sm_ud;
    float* fs  = sm_ud + 16384;
    int b = blockIdx.x, tid = threadIdx.x;
    for (int i = tid; i < HD * HD; i += 256) udt[i] = g_Udt[i];
    for (int i = tid; i < TENC * HD; i += 256) {
        int t = i >> 7, k = i & 127;
        fs[t * 129 + k] = g_fin[(size_t)b * TENC * HD + i];
    }
    __syncthreads();
    for (int u = tid; u < 32 * TENC; u += 256) {
        int t = u % TENC, jq = u / TENC;
        int j0 = 4 * jq;
        float a0 = Udb[j0], a1 = Udb[j0 + 1], a2 = Udb[j0 + 2], a3 = Udb[j0 + 3];
#pragma unroll 8
        for (int k = 0; k < HD; k++) {
            float f = fs[t * 129 + k];
            float4 uu = *(const float4*)(udt + k * HD + j0);
            a0 += f * uu.x; a1 += f * uu.y; a2 += f * uu.z; a3 += f * uu.w;
        }
        size_t base = (size_t)b * HD * TENC;
        g_udTh[base + (size_t)(j0 + 0) * TENC + t] = __float2bfloat16(a0);
        g_udTh[base + (size_t)(j0 + 1) * TENC + t] = __float2bfloat16(a1);
        g_udTh[base + (size_t)(j0 + 2) * TENC + t] = __float2bfloat16(a2);
        g_udTh[base + (size_t)(j0 + 3) * TENC + t] = __float2bfloat16(a3);
    }
}

// ---------------- encoder stage: 1024 threads, 8 groups x 128, G=8, 1 CTA/SM ----------------
template <int K, int KP, int NF, bool PB16>
__global__ __launch_bounds__(NTHS, 1) void stage_kernel(
    const float* __restrict__ inp,
    const float* __restrict__ Ve, const float* __restrict__ Veb,
    const unsigned* __restrict__ W2, const float* __restrict__ bsum,
    const float* __restrict__ Wet, const float* __restrict__ preF,
    float* __restrict__ outb, int ostride) {
    extern __shared__ float sm[];
    constexpr int PRE_FL = PB16 ? (G * TENC * NF / 2) : (G * TENC * NF);
    constexpr int XS_FL  = PB16 ? 0 : (G * TENC * NF1);
    constexpr int O_PRE = 12288;
    constexpr int O_XS  = O_PRE + PRE_FL;
    constexpr int O_HCT = O_XS + XS_FL;
    constexpr int O_WE  = O_HCT + 256 * HCT_STR;
    constexpr int O_WEP = O_WE + 384;
    constexpr int O_SC  = O_WEP + 384;
    constexpr int O_AL  = O_SC + 1056;
    constexpr int O_IP  = O_AL + 1056;
    constexpr int O_GT  = O_IP + KP * 8;
    constexpr int O_PG  = O_GT + 4096;
    constexpr int O_BS  = O_PG + 4608;
    constexpr int O_VV  = O_BS + 512;

    float* wet  = sm;
    float* pres = sm + O_PRE;
    float* xs   = sm + O_XS;
    float* hcT  = sm + O_HCT;
    float* ipK  = sm + O_IP;     // [KP][8]
    float* gates = sm + O_GT;
    float* pg   = sm + O_PG;
    float* bias = sm + O_BS;
    float* vvec = sm + O_VV;

    const int tid = threadIdx.x, bid = blockIdx.x;
    const int p = tid >> 7;          // group 0..7 = batch element
    const int lt = tid & 127;
    const int gw = lt >> 5;
    const int lane = tid & 31;
    const int b = bid * G + p;

    float* weg  = sm + O_WE  + p * 48;
    float* wepg = sm + O_WEP + p * 48;
    float* scg  = sm + O_SC  + p * 132;
    float* alg  = sm + O_AL  + p * 132;

    for (int i = tid; i < 256 * TENC; i += NTHS) wet[i] = Wet[i];
    if (PB16) {
        const unsigned* src = (const unsigned*)(g_pre2h + (size_t)bid * G * TENC * NF2);
        unsigned* dst = (unsigned*)pres;
        for (int i = tid; i < G * TENC * NF2 / 2; i += NTHS) dst[i] = src[i];
    } else {
        const float* src = preF + (size_t)bid * G * TENC * NF;
        for (int i = tid; i < G * TENC * NF; i += NTHS) pres[i] = src[i];
        for (int i = tid; i < G * TENC * NF1; i += NTHS) {
            int g = i / (TENC * NF1);
            int r = i - g * TENC * NF1;
            int t = r / NF1, f = r - t * NF1;
            xs[i] = inp[((size_t)(bid * G + g) * TENC + t) * 18 + f + 1];
        }
    }
    for (int i = tid; i < 256 * HCT_STR; i += NTHS) hcT[i] = 0.f;
    for (int i = tid; i < NG; i += NTHS) bias[i] = bsum[i];
    for (int i = tid; i < TENC; i += NTHS) vvec[i] = Ve[i];
    if (tid == 0) vvec[130] = Veb[0];
    for (int i = tid; i < KP * 8; i += NTHS) ipK[i] = 0.f;
    __syncthreads();

    // A mapping: 48 threads/group = 2 k-halves x 24 ss-pairs
    const int akh = lt / 24;
    const int ass0 = 2 * (lt % 24);

    for (int t = 0; t < TENC; t++) {
        // x prefetch for D
        float xr0 = 0.f, xr1 = 0.f, xr2 = 0.f, xr3 = 0.f, xr4 = 0.f;
        if (gw == 0) {
            if (PB16) {
                const float* xp = g_mid + ((size_t)b * TENC + t) * NF2;
                xr0 = xp[lane]; xr1 = xp[lane + 32];
                xr2 = xp[lane + 64]; xr3 = xp[lane + 96];
                if (lane == 0) xr4 = xp[128];
            } else {
                if (lane < NF) xr0 = xs[p * TENC * NF1 + t * NF1 + lane];
            }
        }
        // A: we projection (48 threads/group, ss-pair fma2, 2-way k-split)
        if (lt < 48) {
            int kb = akh * 128;
            u64 acc = 0ull;
#pragma unroll 8
            for (int kk = 0; kk < 128; kk++) {
                int k = kb + kk;
                u64 wv = *(const u64*)(wet + k * TENC + ass0);
                acc = fma2(wv, dup2(hcT[k * HCT_STR + p]), acc);
            }
            float2 v = unpack2(acc);
            float* dst = akh ? wepg : weg;
            dst[ass0] = v.x;
            dst[ass0 + 1] = v.y;
        }
        barg(p);
        if (lt < 48) weg[lt] += wepg[lt];
        barg(p);
        // B: scores (128 threads/group over NF items)
        {
            float bb = vvec[130];
            for (int f = lt; f < NF; f += 128) {
                float a = 0.f;
                if (PB16) {
                    const __nv_bfloat16* pp =
                        (const __nv_bfloat16*)pres + (p * TENC) * NF + f;
#pragma unroll 4
                    for (int ss = 0; ss < TENC; ss++)
                        a += tanha(weg[ss] + __bfloat162float(pp[ss * NF])) * vvec[ss];
                } else {
                    const float* pp = pres + (p * TENC) * NF + f;
#pragma unroll 4
                    for (int ss = 0; ss < TENC; ss++)
                        a += tanha(weg[ss] + pp[ss * NF]) * vvec[ss];
                }
                scg[f] = a + bb;
            }
        }
        barg(p);
        // softmax + D fused (warp 0 of group) -> ipK [k][8]
        if (gw == 0) {
            warp_softmax(scg, alg, NF, lane);
            __syncwarp();
            if (PB16) {
                ipK[lane * 8 + p]        = xr0 * alg[lane];
                ipK[(lane + 32) * 8 + p] = xr1 * alg[lane + 32];
                ipK[(lane + 64) * 8 + p] = xr2 * alg[lane + 64];
                ipK[(lane + 96) * 8 + p] = xr3 * alg[lane + 96];
                if (lane == 0) ipK[128 * 8 + p] = xr4 * alg[128];
            } else {
                if (lane < NF) ipK[lane * 8 + p] = xr0 * alg[lane];
            }
        }
        __syncthreads();
        gates_gemmW<KP>(W2, bias, ipK, gates, pg, tid);
        __syncthreads();
        // F: cell update, one item per thread
        {
            int g = tid >> 7, j = tid & 127;
            float gi = gates[g * NG + j];
            float gf = gates[g * NG + HD + j];
            float gg = gates[g * NG + 2 * HD + j];
            float go = gates[g * NG + 3 * HD + j];
            float c  = hcT[(128 + j) * HCT_STR + g];
            float c2 = siga(gf) * c + siga(gi) * tanha(gg);
            float h  = siga(go) * tanha(c2);
            hcT[j * HCT_STR + g] = h;
            hcT[(128 + j) * HCT_STR + g] = c2;
            ipK[(NF + j) * 8 + g] = h;
            outb[((size_t)(bid * G + g) * TENC + t) * ostride + j] = h;
        }
        __syncthreads();
    }
}

// ---------------- decoder (round-12 verbatim) ----------------
#define D_O_WDT 0
#define D_O_HCT 32768
#define D_O_WD  35328
#define D_O_SC  36352
#define D_O_AL  36736
#define D_O_IP  37120
#define D_O_GT  39168
#define D_O_PG  43264
#define D_O_BS  47872
#define D_O_VV  48384
#define D_O_VR  48520
#define DEC_SMEM_FL 48656

__global__ __launch_bounds__(NTH, 1) void decoder_kernel(
    const float* __restrict__ Vd, const float* __restrict__ Vdb,
    const float* __restrict__ regW, const float* __restrict__ regb,
    float* __restrict__ out) {
    extern __shared__ float sm[];
    float* wdt  = sm + D_O_WDT;
    float* hcT  = sm + D_O_HCT;
    float* wd   = sm + D_O_WD;
    float* score = sm + D_O_SC;
    float* alpha = sm + D_O_AL;
    float* ipT  = sm + D_O_IP;     // [G][KPD]
    float* gates = sm + D_O_GT;
    float* pg   = sm + D_O_PG;
    float* bias = sm + D_O_BS;
    float* vvec = sm + D_O_VV;
    float* vreg = sm + D_O_VR;
    float* part = gates;

    const int tid = threadIdx.x, bid = blockIdx.x;
    const int wid = tid >> 5, lane = tid & 31;

    for (int i = tid; i < 256 * HD; i += NTH) wdt[i] = g_Wdt[i];
    for (int i = tid; i < 256 * HCT_STR; i += NTH) hcT[i] = 0.f;
    for (int i = tid; i < NG; i += NTH) bias[i] = g_bd[i];
    for (int i = tid; i < KPD * G; i += NTH) ipT[i] = 0.f;
    for (int i = tid; i < HD; i += NTH) { vvec[i] = Vd[i]; vreg[i] = regW[i]; }
    if (tid == 0) { vvec[130] = Vdb[0]; vreg[130] = regb[0]; }
    __syncthreads();

    bool sval = tid < G * TENC;
    int sg = sval ? tid / TENC : 0, stt = sval ? tid % TENC : 0;
    const __nv_bfloat16* up = g_udTh + ((size_t)(bid * G + sg) * HD) * TENC + stt;
    int dg = tid >> 6, dj = (tid & 63) * 2;
    const float* fp = g_fin + ((size_t)(bid * G + dg) * TENC) * HD + dj;
    const int s8 = tid >> 6;
    const int jp = tid & 63, j0 = 2 * jp;

    for (int sd = 0; sd < DSTEPS; sd++) {
        {
            u64 a0 = 0, a1 = 0, a2 = 0, a3 = 0, a4 = 0, a5 = 0, a6 = 0, a7 = 0;
            int kb = s8 * 32;
#pragma unroll 8
            for (int kk = 0; kk < 32; kk++) {
                int k = kb + kk;
                float2 w = *(const float2*)(wdt + k * HD + j0);
                u64 w0 = dup2(w.x), w1 = dup2(w.y);
                const float* hp = hcT + k * HCT_STR;
                u64 h01 = *(const u64*)(hp);
                u64 h23 = *(const u64*)(hp + 2);
                u64 h45 = *(const u64*)(hp + 4);
                u64 h67 = *(const u64*)(hp + 6);
                a0 = fma2(w0, h01, a0); a1 = fma2(w0, h23, a1);
                a2 = fma2(w0, h45, a2); a3 = fma2(w0, h67, a3);
                a4 = fma2(w1, h01, a4); a5 = fma2(w1, h23, a5);
                a6 = fma2(w1, h45, a6); a7 = fma2(w1, h67, a7);
            }
            float* pp = part + s8 * 1024 + j0 * 8;
            float2 r;
            r = unpack2(a0); pp[0] = r.x; pp[1] = r.y;
            r = unpack2(a1); pp[2] = r.x; pp[3] = r.y;
            r = unpack2(a2); pp[4] = r.x; pp[5] = r.y;
            r = unpack2(a3); pp[6] = r.x; pp[7] = r.y;
            pp += 8;
            r = unpack2(a4); pp[0] = r.x; pp[1] = r.y;
            r = unpack2(a5); pp[2] = r.x; pp[3] = r.y;
            r = unpack2(a6); pp[4] = r.x; pp[5] = r.y;
            r = unpack2(a7); pp[6] = r.x; pp[7] = r.y;
        }
        __syncthreads();
#pragma unroll
        for (int u = 0; u < 2; u++) {
            int o = tid + u * NTH;
            float s = 0.f;
#pragma unroll
            for (int q = 0; q < 8; q++) s += part[q * 1024 + o];
            int j = o >> 3, g = o & 7;
            wd[g * HD + j] = s;
        }
        __syncthreads();
        {
            float a = 0.f;
#pragma unroll 4
            for (int j = 0; j < HD; j++)
                a += tanha(wd[sg * HD + j] + __bfloat162float(up[(size_t)j * TENC])) * vvec[j];
            if (sval) score[sg * TENC + stt] = a + vvec[130];
        }
        __syncthreads();
        if (wid < G) warp_softmax(score + wid * TENC, alpha + wid * TENC, TENC, lane);
        __syncthreads();
        {
            float a0 = 0.f, a1 = 0.f;
#pragma unroll 4
            for (int tt = 0; tt < TENC; tt++) {
                float al = alpha[dg * TENC + tt];
                float2 f2 = *(const float2*)(fp + (size_t)tt * HD);
                a0 += al * f2.x; a1 += al * f2.y;
            }
            ipT[dg * KPD + dj] = a0;
            ipT[dg * KPD + dj + 1] = a1;
        }
        __syncthreads();
        gates_gemm5<KPD>(g_W2d, bias, ipT, gates, pg, tid);
        __syncthreads();
        for (int idx = tid; idx < G * HD; idx += NTH) {
            int g = idx >> 7, j = idx & 127;
            float gi = gates[g * NG + j];
            float gf = gates[g * NG + HD + j];
            float gg = gates[g * NG + 2 * HD + j];
            float go = gates[g * NG + 3 * HD + j];
            float c  = hcT[(128 + j) * HCT_STR + g];
            float c2 = siga(gf) * c + siga(gi) * tanha(gg);
            float h  = siga(go) * tanha(c2);
            hcT[j * HCT_STR + g] = h;
            hcT[(128 + j) * HCT_STR + g] = c2;
            ipT[g * KPD + HD + j] = h;
        }
        __syncthreads();
        if (sd >= DSTEPS - TDEC && wid < G) {
            float a = 0.f;
#pragma unroll
            for (int r = 0; r < 4; r++)
                a += hcT[(lane + 32 * r) * HCT_STR + wid] * vreg[lane + 32 * r];
#pragma unroll
            for (int o = 16; o; o >>= 1) a += __shfl_xor_sync(0xffffffffu, a, o);
            if (lane == 0)
                out[(size_t)(bid * G + wid) * TDEC + (sd - (DSTEPS - TDEC))] = a + vreg[130];
        }
    }
}

// ---------------- launch ----------------
extern "C" void kernel_launch(void* const* d_in, const int* in_sizes, int n_in,
                              void* d_out, int out_size) {
    const float* input_p_q = (const float*)d_in[0];
    const float* label_p   = (const float*)d_in[1];
    const float* Ue1_W = (const float*)d_in[2];
    const float* Ue1_b = (const float*)d_in[3];
    const float* We1_W = (const float*)d_in[4];
    const float* Ve1_W = (const float*)d_in[5];
    const float* Ve1_b = (const float*)d_in[6];
    const float* Ue2_W = (const float*)d_in[7];
    const float* Ue2_b = (const float*)d_in[8];
    const float* We2_W = (const float*)d_in[9];
    const float* Ve2_W = (const float*)d_in[10];
    const float* Ve2_b = (const float*)d_in[11];
    const float* Ud_W  = (const float*)d_in[12];
    const float* Ud_b  = (const float*)d_in[13];
    const float* Wd_W  = (const float*)d_in[14];
    const float* Vd_W  = (const float*)d_in[15];
    const float* Vd_b  = (const float*)d_in[16];
    const float* e1_Wih = (const float*)d_in[17];
    const float* e1_Whh = (const float*)d_in[18];
    const float* e1_bih = (const float*)d_in[19];
    const float* e1_bhh = (const float*)d_in[20];
    const float* e2_Wih = (const float*)d_in[21];
    const float* e2_Whh = (const float*)d_in[22];
    const float* e2_bih = (const float*)d_in[23];
    const float* e2_bhh = (const float*)d_in[24];
    const float* d_Wih  = (const float*)d_in[25];
    const float* d_Whh  = (const float*)d_in[26];
    const float* d_bih  = (const float*)d_in[27];
    const float* d_bhh  = (const float*)d_in[28];
    const float* reg_W  = (const float*)d_in[29];
    const float* reg_b  = (const float*)d_in[30];
    float* out = (float*)d_out;

    unsigned *p_W21, *p_W22;
    float *p_Wet1, *p_Wet2;
    float *p_b1, *p_b2, *p_pre1, *p_mid, *p_fin;
    cudaGetSymbolAddress((void**)&p_W21, g_W21);
    cudaGetSymbolAddress((void**)&p_W22, g_W22);
    cudaGetSymbolAddress((void**)&p_Wet1, g_Wet1);
    cudaGetSymbolAddress((void**)&p_Wet2, g_Wet2);
    cudaGetSymbolAddress((void**)&p_b1, g_b1);
    cudaGetSymbolAddress((void**)&p_b2, g_b2);
    cudaGetSymbolAddress((void**)&p_pre1, g_pre1);
    cudaGetSymbolAddress((void**)&p_mid, g_mid);
    cudaGetSymbolAddress((void**)&p_fin, g_fin);

    const int S1_FL = 12288 + (G*TENC*NF1) + (G*TENC*NF1) + 2560 + 384 + 384
                      + 1056 + 1056 + KP1 * 8 + 4096 + 4608 + 512 + 136;
    const int S2_FL = 12288 + (G*TENC*NF2/2) + 2560 + 384 + 384
                      + 1056 + 1056 + KP2 * 8 + 4096 + 4608 + 512 + 136;
    const int STAGE1_SMEM = S1_FL * 4;
    const int STAGE2_SMEM = S2_FL * 4;
    const int DEC_SMEM    = DEC_SMEM_FL * 4;
    const int UD_SMEM     = (16384 + TENC * 129) * 4;

    cudaFuncSetAttribute((const void*)stage_kernel<K1, KP1, NF1, false>,
                         cudaFuncAttributeMaxDynamicSharedMemorySize, STAGE1_SMEM);
    cudaFuncSetAttribute((const void*)stage_kernel<K2, KP2, NF2, true>,
                         cudaFuncAttributeMaxDynamicSharedMemorySize, STAGE2_SMEM);
    cudaFuncSetAttribute((const void*)decoder_kernel,
                         cudaFuncAttributeMaxDynamicSharedMemorySize, DEC_SMEM);
    cudaFuncSetAttribute((const void*)ud_kernel,
                         cudaFuncAttributeMaxDynamicSharedMemorySize, UD_SMEM);

    nop_kernel<<<1, 32>>>();   // keeps ncu capture slot on stage1
    setup_kernel<<<128, 256>>>(e1_Wih, e1_Whh, e2_Wih, e2_Whh, d_Wih, d_Whh,
                               We1_W, We2_W, Wd_W, Ud_W,
                               e1_bih, e1_bhh, e2_bih, e2_bhh, d_bih, d_bhh);
    pre1_kernel<<<BTOT, 256>>>(input_p_q, label_p, Ue1_W, Ue1_b);
    stage_kernel<K1, KP1, NF1, false><<<NCTA, NTHS, STAGE1_SMEM>>>(
        input_p_q, Ve1_W, Ve1_b, p_W21, p_b1, p_Wet1, p_pre1, p_mid, NF2);
    pre2_kernel<<<BTOT, 256>>>(Ue2_W, Ue2_b);
    stage_kernel<K2, KP2, NF2, true><<<NCTA, NTHS, STAGE2_SMEM>>>(
        input_p_q, Ve2_W, Ve2_b, p_W22, p_b2, p_Wet2, nullptr, p_fin, HD);
    ud_kernel<<<BTOT, 256, UD_SMEM>>>(Ud_b);
    decoder_kernel<<<NCTA, NTH, DEC_SMEM>>>(Vd_W, Vd_b, reg_W, reg_b, out);
}

// round 15
// speedup vs baseline: 1.3783x; 1.2018x over previous
#include <cuda_runtime.h>
#include <cuda_bf16.h>

#define TENC 48
#define TDEC 24
#define DSTEPS 30
#define HD 128
#define NF1 17
#define NF2 129
#define KP1 160       // [h(128) | x(17) pad->32]
#define KP2 272       // [h(128) | x(129) pad->144]
#define KPD 256
#define XH1 8         // x u32-rows per half (stage1: rows 64..79)
#define XH2 36        // stage2: rows 64..135
#define G 8
#define NCTA 128
#define NTH 512
#define NG 512
#define BTOT 1024
#define HCT_STR 10

typedef unsigned long long u64;

// ---------------- device scratch (allocation-free) ----------------
__device__ unsigned g_W21[(KP1 / 2) * NG];   // [row][n], row=k-pair, order [h|x]
__device__ unsigned g_W22[(KP2 / 2) * NG];
__device__ unsigned g_W2d[(KPD / 2) * NG];   // decoder: original [din|h] order
__device__ float g_Wet1[256 * TENC];
__device__ float g_Wet2[256 * TENC];
__device__ float g_Wdt[256 * HD];
__device__ float g_Udt[HD * HD];
__device__ float g_b1[NG], g_b2[NG], g_bd[NG];
__device__ float g_pre1[BTOT * TENC * NF1];           // [b][s][f] fp32
__device__ __nv_bfloat16 g_pre2h[BTOT * TENC * NF2];  // [b][s][f] bf16
__device__ float g_mid[BTOT * TENC * NF2];
__device__ float g_fin[BTOT * TENC * HD];
__device__ __nv_bfloat16 g_udTh[BTOT * HD * TENC];

// ---------------- math helpers ----------------
__device__ __forceinline__ float tanha(float x) {
    float y; asm("tanh.approx.f32 %0, %1;" : "=f"(y) : "f"(x)); return y;
}
__device__ __forceinline__ float siga(float x) {
    return fmaf(tanha(0.5f * x), 0.5f, 0.5f);
}
__device__ __forceinline__ u64 fma2(u64 a, u64 b, u64 c) {
    u64 d; asm("fma.rn.f32x2 %0, %1, %2, %3;" : "=l"(d) : "l"(a), "l"(b), "l"(c)); return d;
}
__device__ __forceinline__ u64 dup2(float x) {
    u64 d; unsigned r = __float_as_uint(x);
    asm("mov.b64 %0, {%1, %1};" : "=l"(d) : "r"(r)); return d;
}
__device__ __forceinline__ float2 unpack2(u64 a) {
    unsigned l, h;
    asm("mov.b64 {%0, %1}, %2;" : "=r"(l), "=r"(h) : "l"(a));
    return make_float2(__uint_as_float(l), __uint_as_float(h));
}
__device__ __forceinline__ u64 bf2f2(unsigned w) {
    unsigned lo = w << 16;
    unsigned hi = w & 0xffff0000u;
    u64 d;
    asm("mov.b64 %0, {%1, %2};" : "=l"(d) : "r"(lo), "r"(hi));
    return d;
}
__device__ __forceinline__ void barh() {   // lower-half barrier
    asm volatile("bar.sync 1, 256;" ::: "memory");
}

__device__ __forceinline__ void warp_softmax(const float* score_row, float* alpha_row,
                                             int F, int lane) {
    float mx = -1e30f;
    for (int f = lane; f < F; f += 32) mx = fmaxf(mx, score_row[f]);
#pragma unroll
    for (int o = 16; o; o >>= 1) mx = fmaxf(mx, __shfl_xor_sync(0xffffffffu, mx, o));
    float sm = 0.f;
    for (int f = lane; f < F; f += 32) {
        float e = __expf(score_row[f] - mx);
        alpha_row[f] = e;
        sm += e;
    }
#pragma unroll
    for (int o = 16; o; o >>= 1) sm += __shfl_xor_sync(0xffffffffu, sm, o);
    float inv = __fdividef(1.f, sm);
    for (int f = lane; f < F; f += 32) alpha_row[f] *= inv;
}

__global__ void nop_kernel() {}

// ---- partial gate GEMM over u32-row range [r0, r0+NR): 256 threads, 2 cols ----
// acc written raw to out as out[n*9+g] (partial) or combined by caller.
template <int KP, int NR>
__device__ __forceinline__ void gemm_rows(const unsigned* __restrict__ W2, int r0,
                                          const float* __restrict__ ipT,   // [g][KP]
                                          int lt, u64* acc0, u64* acc1) {
    const int n0 = lt * 2;
    const u64* wp = (const u64*)(W2 + (size_t)r0 * NG) + lt;
    const float* ipb = ipT + 2 * r0;
#pragma unroll 1
    for (int b = 0; b < NR; b += 4) {
        u64 w4[4];
#pragma unroll
        for (int i = 0; i < 4; i++) w4[i] = wp[(size_t)(b + i) * (NG / 2)];
        u64 wn0[4], wn1[4];
#pragma unroll
        for (int i = 0; i < 4; i++) {
            wn0[i] = bf2f2((unsigned)w4[i]);
            wn1[i] = bf2f2((unsigned)(w4[i] >> 32));
        }
        const float* ipk = ipb + 2 * b;
#pragma unroll
        for (int g = 0; g < 8; g++) {
            const float* r = ipk + g * KP;
            ulonglong2 pA = *(const ulonglong2*)(r);
            ulonglong2 pB = *(const ulonglong2*)(r + 4);
            acc0[g] = fma2(wn0[0], pA.x, acc0[g]);
            acc0[g] = fma2(wn0[1], pA.y, acc0[g]);
            acc0[g] = fma2(wn0[2], pB.x, acc0[g]);
            acc0[g] = fma2(wn0[3], pB.y, acc0[g]);
            acc1[g] = fma2(wn1[0], pA.x, acc1[g]);
            acc1[g] = fma2(wn1[1], pA.y, acc1[g]);
            acc1[g] = fma2(wn1[2], pB.x, acc1[g]);
            acc1[g] = fma2(wn1[3], pB.y, acc1[g]);
        }
    }
    (void)n0;
}

// ---- decoder gate GEMM (round-12 verbatim) ----
template <int KP>
__device__ __forceinline__ void gates_gemm5(const unsigned* __restrict__ W2,
                                            const float* __restrict__ bias,
                                            const float* __restrict__ ipT,
                                            float* __restrict__ gates,
                                            float* __restrict__ pg, int tid) {
    constexpr int KKH = KP / 4;
    const int half = tid >> 8;
    const int lt = tid & 255;
    const int n0 = lt * 2;
    const int kk0 = half * KKH;
    u64 acc0[8], acc1[8];
#pragma unroll
    for (int g = 0; g < 8; g++) { acc0[g] = 0ull; acc1[g] = 0ull; }
    gemm_rows<KP, KKH>(W2, kk0, ipT, lt, acc0, acc1);
    if (half) {
        float* pp = pg + n0 * 9;
        float* pq = pg + (n0 + 1) * 9;
#pragma unroll
        for (int g = 0; g < 8; g++) {
            float2 r0 = unpack2(acc0[g]);
            float2 r1 = unpack2(acc1[g]);
            pp[g] = r0.x + r0.y;
            pq[g] = r1.x + r1.y;
        }
    }
    __syncthreads();
    if (!half) {
        const float* pp = pg + n0 * 9;
        const float* pq = pg + (n0 + 1) * 9;
        float b0 = bias[n0], b1 = bias[n0 + 1];
#pragma unroll
        for (int g = 0; g < 8; g++) {
            float2 r0 = unpack2(acc0[g]);
            float2 r1 = unpack2(acc1[g]);
            gates[g * NG + n0]     = r0.x + r0.y + pp[g] + b0;
            gates[g * NG + n0 + 1] = r1.x + r1.y + pq[g] + b1;
        }
    }
}

// ---------------- setup ----------------
__global__ void setup_kernel(
    const float* __restrict__ e1_Wih, const float* __restrict__ e1_Whh,
    const float* __restrict__ e2_Wih, const float* __restrict__ e2_Whh,
    const float* __restrict__ d_Wih,  const float* __restrict__ d_Whh,
    const float* __restrict__ We1,    const float* __restrict__ We2,
    const float* __restrict__ Wd,     const float* __restrict__ Ud,
    const float* __restrict__ e1_bih, const float* __restrict__ e1_bhh,
    const float* __restrict__ e2_bih, const float* __restrict__ e2_bhh,
    const float* __restrict__ d_bih,  const float* __restrict__ d_bhh) {
    int tid = blockIdx.x * blockDim.x + threadIdx.x;
    int nt = gridDim.x * blockDim.x;
    // stage weights: order [h(128) | x(NF)]
    for (int i = tid; i < (KP1 / 2) * NG; i += nt) {
        int kk = i / NG, n = i % NG;
        float v[2];
#pragma unroll
        for (int q = 0; q < 2; q++) {
            int k = 2 * kk + q;
            if (k < HD) v[q] = e1_Whh[n * HD + k];
            else if (k - HD < NF1) v[q] = e1_Wih[n * NF1 + (k - HD)];
            else v[q] = 0.f;
        }
        g_W21[i] = (unsigned)__bfloat16_as_ushort(__float2bfloat16(v[0]))
                 | ((unsigned)__bfloat16_as_ushort(__float2bfloat16(v[1])) << 16);
    }
    for (int i = tid; i < (KP2 / 2) * NG; i += nt) {
        int kk = i / NG, n = i % NG;
        float v[2];
#pragma unroll
        for (int q = 0; q < 2; q++) {
            int k = 2 * kk + q;
            if (k < HD) v[q] = e2_Whh[n * HD + k];
            else if (k - HD < NF2) v[q] = e2_Wih[n * NF2 + (k - HD)];
            else v[q] = 0.f;
        }
        g_W22[i] = (unsigned)__bfloat16_as_ushort(__float2bfloat16(v[0]))
                 | ((unsigned)__bfloat16_as_ushort(__float2bfloat16(v[1])) << 16);
    }
    for (int i = tid; i < (KPD / 2) * NG; i += nt) {
        int kk = i / NG, n = i % NG;
        int k0 = 2 * kk, k1 = 2 * kk + 1;
        float v0 = (k0 < HD) ? d_Wih[n * HD + k0] : d_Whh[n * HD + (k0 - HD)];
        float v1 = (k1 < HD) ? d_Wih[n * HD + k1] : d_Whh[n * HD + (k1 - HD)];
        g_W2d[i] = (unsigned)__bfloat16_as_ushort(__float2bfloat16(v0))
                 | ((unsigned)__bfloat16_as_ushort(__float2bfloat16(v1)) << 16);
    }
    for (int i = tid; i < 256 * TENC; i += nt) {
        int k = i / TENC, ss = i % TENC;
        g_Wet1[i] = We1[ss * 256 + k];
        g_Wet2[i] = We2[ss * 256 + k];
    }
    for (int i = tid; i < 256 * HD; i += nt) {
        int k = i / HD, j = i % HD;
        g_Wdt[i] = Wd[j * 256 + k];
    }
    for (int i = tid; i < HD * HD; i += nt) {
        int k = i / HD, j = i % HD;
        g_Udt[i] = Ud[j * HD + k];
    }
    for (int i = tid; i < NG; i += nt) {
        g_b1[i] = e1_bih[i] + e1_bhh[i];
        g_b2[i] = e2_bih[i] + e2_bhh[i];
        g_bd[i] = d_bih[i] + d_bhh[i];
    }
}

// ---------------- pre1 ----------------
__global__ __launch_bounds__(256) void pre1_kernel(
    const float* __restrict__ inp, const float* __restrict__ lab,
    const float* __restrict__ Ue1, const float* __restrict__ Ue1b) {
    __shared__ float xs[TENC * NF1];
    __shared__ float ue[TENC * TENC];
    int b = blockIdx.x, tid = threadIdx.x;
    for (int i = tid; i < TENC * NF1; i += 256) {
        int t = i / NF1, f = i % NF1;
        xs[i] = inp[((size_t)b * TENC + t) * 18 + f + 1];
    }
    for (int i = tid; i < TENC * TENC; i += 256) ue[i] = Ue1[i];
    for (int i = tid; i < TENC; i += 256)
        g_mid[((size_t)b * TENC + i) * NF2 + HD] = lab[(size_t)b * TENC + i];
    __syncthreads();
    for (int i = tid; i < TENC * NF1; i += 256) {
        int ss = i / NF1, f = i % NF1;
        float a = 0.f;
#pragma unroll 8
        for (int t = 0; t < TENC; t++) a += xs[t * NF1 + f] * ue[ss * TENC + t];
        g_pre1[(size_t)b * TENC * NF1 + i] = a + Ue1b[ss];
    }
}

// ---------------- pre2 (bf16 out) ----------------
__global__ __launch_bounds__(256) void pre2_kernel(
    const float* __restrict__ Ue2, const float* __restrict__ Ue2b) {
    __shared__ float ms[TENC * 130];
    __shared__ float ue[TENC * TENC];
    int b = blockIdx.x, tid = threadIdx.x;
    for (int i = tid; i < TENC * NF2; i += 256) {
        int t = i / NF2, f = i % NF2;
        ms[t * 130 + f] = g_mid[(size_t)b * TENC * NF2 + i];
    }
    for (int i = tid; i < TENC; i += 256) ms[i * 130 + 129] = 0.f;
    for (int i = tid; i < TENC * TENC; i += 256) ue[i] = Ue2[i];
    __syncthreads();
    for (int u = tid; u < TENC * 65; u += 256) {
        int ss = u / 65, q = u % 65;
        int f0 = 2 * q;
        u64 acc = 0ull;
#pragma unroll 8
        for (int t = 0; t < TENC; t++)
            acc = fma2(dup2(ue[ss * TENC + t]), *(const u64*)(ms + t * 130 + f0), acc);
        float2 r = unpack2(acc);
        float bb = Ue2b[ss];
        size_t base = (size_t)b * TENC * NF2 + ss * NF2;
        g_pre2h[base + f0] = __float2bfloat16(r.x + bb);
        if (f0 < 128) g_pre2h[base + f0 + 1] = __float2bfloat16(r.y + bb);
    }
}

// ---------------- ud (bf16 out, transposed) ----------------
__global__ __launch_bounds__(256) void ud_kernel(const float* __restrict__ Udb) {
    extern __shared__ float sm_ud[];
    float* udt = sm_ud;
    float* fs  = sm_ud + 16384;
    int b = blockIdx.x, tid = threadIdx.x;
    for (int i = tid; i < HD * HD; i += 256) udt[i] = g_Udt[i];
    for (int i = tid; i < TENC * HD; i += 256) {
        int t = i >> 7, k = i & 127;
        fs[t * 129 + k] = g_fin[(size_t)b * TENC * HD + i];
    }
    __syncthreads();
    for (int u = tid; u < 32 * TENC; u += 256) {
        int t = u % TENC, jq = u / TENC;
        int j0 = 4 * jq;
        float a0 = Udb[j0], a1 = Udb[j0 + 1], a2 = Udb[j0 + 2], a3 = Udb[j0 + 3];
#pragma unroll 8
        for (int k = 0; k < HD; k++) {
            float f = fs[t * 129 + k];
            float4 uu = *(const float4*)(udt + k * HD + j0);
            a0 += f * uu.x; a1 += f * uu.y; a2 += f * uu.z; a3 += f * uu.w;
        }
        size_t base = (size_t)b * HD * TENC;
        g_udTh[base + (size_t)(j0 + 0) * TENC + t] = __float2bfloat16(a0);
        g_udTh[base + (size_t)(j0 + 1) * TENC + t] = __float2bfloat16(a1);
        g_udTh[base + (size_t)(j0 + 2) * TENC + t] = __float2bfloat16(a2);
        g_udTh[base + (size_t)(j0 + 3) * TENC + t] = __float2bfloat16(a3);
    }
}

// ---------------- encoder stage: warp-specialized h-GEMM overlap ----------------
// lower 256: attention for all 8 elements; upper 256: h-GEMM (rows 0..63).
template <int KP, int NF, int XH, bool PB16>
__global__ __launch_bounds__(NTH, 1) void stage_kernel(
    const float* __restrict__ inp,
    const float* __restrict__ Ve, const float* __restrict__ Veb,
    const unsigned* __restrict__ W2, const float* __restrict__ bsum,
    const float* __restrict__ Wet, const float* __restrict__ preF,
    float* __restrict__ outb, int ostride) {
    extern __shared__ float sm[];
    constexpr int PRE_FL = PB16 ? (G * TENC * NF / 2) : (G * TENC * NF);
    constexpr int XS_FL  = PB16 ? 0 : (G * TENC * NF1);
    constexpr int O_PRE = 12288;
    constexpr int O_XS  = O_PRE + PRE_FL;
    constexpr int O_HCT = O_XS + XS_FL;
    constexpr int O_WE  = O_HCT + 256 * HCT_STR;
    constexpr int O_SC  = O_WE + 384;
    constexpr int O_AL  = O_SC + 1056;
    constexpr int O_IP  = O_AL + 1056;
    constexpr int O_GT  = O_IP + KP * 8;
    constexpr int O_PG  = O_GT + 4096;
    constexpr int O_BS  = O_PG + 4608;
    constexpr int O_VV  = O_BS + 512;

    float* wet  = sm;
    float* pres = sm + O_PRE;
    float* xs   = sm + O_XS;
    float* hcT  = sm + O_HCT;
    float* we   = sm + O_WE;     // [8][48]
    float* sc   = sm + O_SC;     // [8][132]
    float* al   = sm + O_AL;
    float* ipT  = sm + O_IP;     // [g][KP], h at 0..127, x at 128..
    float* gates = sm + O_GT;
    float* pg   = sm + O_PG;     // h-GEMM partials [NG][9]
    float* bias = sm + O_BS;
    float* vvec = sm + O_VV;

    const int tid = threadIdx.x, bid = blockIdx.x;
    const int lower = (tid < 256);
    const int lt = tid & 255;
    const int lw = lt >> 5;          // warp within half
    const int lane = tid & 31;

    for (int i = tid; i < 256 * TENC; i += NTH) wet[i] = Wet[i];
    if (PB16) {
        const unsigned* src = (const unsigned*)(g_pre2h + (size_t)bid * G * TENC * NF2);
        unsigned* dst = (unsigned*)pres;
        for (int i = tid; i < G * TENC * NF2 / 2; i += NTH) dst[i] = src[i];
    } else {
        const float* src = preF + (size_t)bid * G * TENC * NF;
        for (int i = tid; i < G * TENC * NF; i += NTH) pres[i] = src[i];
        for (int i = tid; i < G * TENC * NF1; i += NTH) {
            int g = i / (TENC * NF1);
            int r = i - g * TENC * NF1;
            int t = r / NF1, f = r - t * NF1;
            xs[i] = inp[((size_t)(bid * G + g) * TENC + t) * 18 + f + 1];
        }
    }
    for (int i = tid; i < 256 * HCT_STR; i += NTH) hcT[i] = 0.f;
    for (int i = tid; i < NG; i += NTH) bias[i] = bsum[i];
    for (int i = tid; i < TENC; i += NTH) vvec[i] = Ve[i];
    if (tid == 0) vvec[130] = Veb[0];
    for (int i = tid; i < KP * 8; i += NTH) ipT[i] = 0.f;
    __syncthreads();

    // A mapping (lower): 192 threads = 8 elements x 24 ss-pairs
    const int ae = lt / 24;
    const int ass0 = 2 * (lt % 24);

    for (int t = 0; t < TENC; t++) {
        if (lower) {
            // x prefetch for D (warp lw handles element lw)
            float xr0 = 0.f, xr1 = 0.f, xr2 = 0.f, xr3 = 0.f, xr4 = 0.f;
            if (PB16) {
                const float* xp = g_mid + ((size_t)(bid * G + lw) * TENC + t) * NF2;
                xr0 = xp[lane]; xr1 = xp[lane + 32];
                xr2 = xp[lane + 64]; xr3 = xp[lane + 96];
                if (lane == 0) xr4 = xp[128];
            } else {
                if (lane < NF) xr0 = xs[lw * TENC * NF1 + t * NF1 + lane];
            }
            // A: we projection, dual accumulators
            if (lt < 192) {
                u64 acc0 = 0ull, acc1 = 0ull;
#pragma unroll 4
                for (int kk = 0; kk < 128; kk++) {
                    u64 w0 = *(const u64*)(wet + kk * TENC + ass0);
                    u64 w1 = *(const u64*)(wet + (kk + 128) * TENC + ass0);
                    acc0 = fma2(w0, dup2(hcT[kk * HCT_STR + ae]), acc0);
                    acc1 = fma2(w1, dup2(hcT[(kk + 128) * HCT_STR + ae]), acc1);
                }
                float2 v0 = unpack2(acc0);
                float2 v1 = unpack2(acc1);
                we[ae * 48 + ass0]     = v0.x + v1.x;
                we[ae * 48 + ass0 + 1] = v0.y + v1.y;
            }
            barh();
            // B: scores (8*NF items on 256 threads)
            {
                float bb = vvec[130];
                for (int idx = lt; idx < G * NF; idx += 256) {
                    int e = idx / NF, f = idx - e * NF;
                    float a = 0.f;
                    if (PB16) {
                        const __nv_bfloat16* pp =
                            (const __nv_bfloat16*)pres + (e * TENC) * NF + f;
#pragma unroll 4
                        for (int ss = 0; ss < TENC; ss++)
                            a += tanha(we[e * 48 + ss] + __bfloat162float(pp[ss * NF])) * vvec[ss];
                    } else {
                        const float* pp = pres + (e * TENC) * NF + f;
#pragma unroll 4
                        for (int ss = 0; ss < TENC; ss++)
                            a += tanha(we[e * 48 + ss] + pp[ss * NF]) * vvec[ss];
                    }
                    sc[e * 132 + f] = a + bb;
                }
            }
            barh();
            // softmax + D (warp lw = element lw), x rows at ipT offset 128
            warp_softmax(sc + lw * 132, al + lw * 132, NF, lane);
            __syncwarp();
            if (PB16) {
                ipT[lw * KP + 128 + lane]      = xr0 * al[lw * 132 + lane];
                ipT[lw * KP + 128 + lane + 32] = xr1 * al[lw * 132 + lane + 32];
                ipT[lw * KP + 128 + lane + 64] = xr2 * al[lw * 132 + lane + 64];
                ipT[lw * KP + 128 + lane + 96] = xr3 * al[lw * 132 + lane + 96];
                if (lane == 0) ipT[lw * KP + 256] = xr4 * al[lw * 132 + 128];
            } else {
                if (lane < NF) ipT[lw * KP + 128 + lane] = xr0 * al[lw * 132 + lane];
            }
        } else {
            // upper 256: h-GEMM rows 0..63 (k 0..127), write partials to pg
            u64 acc0[8], acc1[8];
#pragma unroll
            for (int g = 0; g < 8; g++) { acc0[g] = 0ull; acc1[g] = 0ull; }
            gemm_rows<KP, 64>(W2, 0, ipT, lt, acc0, acc1);
            const int n0 = lt * 2;
            float* pp = pg + n0 * 9;
            float* pq = pg + (n0 + 1) * 9;
#pragma unroll
            for (int g = 0; g < 8; g++) {
                float2 r0 = unpack2(acc0[g]);
                float2 r1 = unpack2(acc1[g]);
                pp[g] = r0.x + r0.y;
                pq[g] = r1.x + r1.y;
            }
        }
        __syncthreads();
        // x-GEMM: rows 64..64+2*XH-1, 2-way split across halves
        {
            const int half = tid >> 8;
            u64 acc0[8], acc1[8];
#pragma unroll
            for (int g = 0; g < 8; g++) { acc0[g] = 0ull; acc1[g] = 0ull; }
            gemm_rows<KP, XH>(W2, 64 + half * XH, ipT, lt, acc0, acc1);
            const int n0 = lt * 2;
            if (half) {
#pragma unroll
                for (int g = 0; g < 8; g++) {
                    float2 r0 = unpack2(acc0[g]);
                    float2 r1 = unpack2(acc1[g]);
                    gates[g * NG + n0]     = r0.x + r0.y;
                    gates[g * NG + n0 + 1] = r1.x + r1.y;
                }
            }
            __syncthreads();
            if (!half) {
                const float* pp = pg + n0 * 9;
                const float* pq = pg + (n0 + 1) * 9;
                float b0 = bias[n0], b1 = bias[n0 + 1];
#pragma unroll
                for (int g = 0; g < 8; g++) {
                    float2 r0 = unpack2(acc0[g]);
                    float2 r1 = unpack2(acc1[g]);
                    gates[g * NG + n0]     += r0.x + r0.y + pp[g] + b0;
                    gates[g * NG + n0 + 1] += r1.x + r1.y + pq[g] + b1;
                }
            }
        }
        __syncthreads();
        // F: cell update, 2 items/thread; h -> ipT rows 0..127
#pragma unroll
        for (int u = 0; u < 2; u++) {
            int idx = tid + u * NTH;
            int g = idx >> 7, j = idx & 127;
            float gi = gates[g * NG + j];
            float gf = gates[g * NG + HD + j];
            float gg = gates[g * NG + 2 * HD + j];
            float go = gates[g * NG + 3 * HD + j];
            float c  = hcT[(128 + j) * HCT_STR + g];
            float c2 = siga(gf) * c + siga(gi) * tanha(gg);
            float h  = siga(go) * tanha(c2);
            hcT[j * HCT_STR + g] = h;
            hcT[(128 + j) * HCT_STR + g] = c2;
            ipT[g * KP + j] = h;
            outb[((size_t)(bid * G + g) * TENC + t) * ostride + j] = h;
        }
        __syncthreads();
    }
}

// ---------------- decoder (round-12 verbatim) ----------------
#define D_O_WDT 0
#define D_O_HCT 32768
#define D_O_WD  35328
#define D_O_SC  36352
#define D_O_AL  36736
#define D_O_IP  37120
#define D_O_GT  39168
#define D_O_PG  43264
#define D_O_BS  47872
#define D_O_VV  48384
#define D_O_VR  48520
#define DEC_SMEM_FL 48656

__global__ __launch_bounds__(NTH, 1) void decoder_kernel(
    const float* __restrict__ Vd, const float* __restrict__ Vdb,
    const float* __restrict__ regW, const float* __restrict__ regb,
    float* __restrict__ out) {
    extern __shared__ float sm[];
    float* wdt  = sm + D_O_WDT;
    float* hcT  = sm + D_O_HCT;
    float* wd   = sm + D_O_WD;
    float* score = sm + D_O_SC;
    float* alpha = sm + D_O_AL;
    float* ipT  = sm + D_O_IP;
    float* gates = sm + D_O_GT;
    float* pg   = sm + D_O_PG;
    float* bias = sm + D_O_BS;
    float* vvec = sm + D_O_VV;
    float* vreg = sm + D_O_VR;
    float* part = gates;

    const int tid = threadIdx.x, bid = blockIdx.x;
    const int wid = tid >> 5, lane = tid & 31;

    for (int i = tid; i < 256 * HD; i += NTH) wdt[i] = g_Wdt[i];
    for (int i = tid; i < 256 * HCT_STR; i += NTH) hcT[i] = 0.f;
    for (int i = tid; i < NG; i += NTH) bias[i] = g_bd[i];
    for (int i = tid; i < KPD * G; i += NTH) ipT[i] = 0.f;
    for (int i = tid; i < HD; i += NTH) { vvec[i] = Vd[i]; vreg[i] = regW[i]; }
    if (tid == 0) { vvec[130] = Vdb[0]; vreg[130] = regb[0]; }
    __syncthreads();

    bool sval = tid < G * TENC;
    int sg = sval ? tid / TENC : 0, stt = sval ? tid % TENC : 0;
    const __nv_bfloat16* up = g_udTh + ((size_t)(bid * G + sg) * HD) * TENC + stt;
    int dg = tid >> 6, dj = (tid & 63) * 2;
    const float* fp = g_fin + ((size_t)(bid * G + dg) * TENC) * HD + dj;
    const int s8 = tid >> 6;
    const int jp = tid & 63, j0 = 2 * jp;

    for (int sd = 0; sd < DSTEPS; sd++) {
        {
            u64 a0 = 0, a1 = 0, a2 = 0, a3 = 0, a4 = 0, a5 = 0, a6 = 0, a7 = 0;
            int kb = s8 * 32;
#pragma unroll 8
            for (int kk = 0; kk < 32; kk++) {
                int k = kb + kk;
                float2 w = *(const float2*)(wdt + k * HD + j0);
                u64 w0 = dup2(w.x), w1 = dup2(w.y);
                const float* hp = hcT + k * HCT_STR;
                u64 h01 = *(const u64*)(hp);
                u64 h23 = *(const u64*)(hp + 2);
                u64 h45 = *(const u64*)(hp + 4);
                u64 h67 = *(const u64*)(hp + 6);
                a0 = fma2(w0, h01, a0); a1 = fma2(w0, h23, a1);
                a2 = fma2(w0, h45, a2); a3 = fma2(w0, h67, a3);
                a4 = fma2(w1, h01, a4); a5 = fma2(w1, h23, a5);
                a6 = fma2(w1, h45, a6); a7 = fma2(w1, h67, a7);
            }
            float* pp = part + s8 * 1024 + j0 * 8;
            float2 r;
            r = unpack2(a0); pp[0] = r.x; pp[1] = r.y;
            r = unpack2(a1); pp[2] = r.x; pp[3] = r.y;
            r = unpack2(a2); pp[4] = r.x; pp[5] = r.y;
            r = unpack2(a3); pp[6] = r.x; pp[7] = r.y;
            pp += 8;
            r = unpack2(a4); pp[0] = r.x; pp[1] = r.y;
            r = unpack2(a5); pp[2] = r.x; pp[3] = r.y;
            r = unpack2(a6); pp[4] = r.x; pp[5] = r.y;
            r = unpack2(a7); pp[6] = r.x; pp[7] = r.y;
        }
        __syncthreads();
#pragma unroll
        for (int u = 0; u < 2; u++) {
            int o = tid + u * NTH;
            float s = 0.f;
#pragma unroll
            for (int q = 0; q < 8; q++) s += part[q * 1024 + o];
            int j = o >> 3, g = o & 7;
            wd[g * HD + j] = s;
        }
        __syncthreads();
        {
            float a = 0.f;
#pragma unroll 4
            for (int j = 0; j < HD; j++)
                a += tanha(wd[sg * HD + j] + __bfloat162float(up[(size_t)j * TENC])) * vvec[j];
            if (sval) score[sg * TENC + stt] = a + vvec[130];
        }
        __syncthreads();
        if (wid < G) warp_softmax(score + wid * TENC, alpha + wid * TENC, TENC, lane);
        __syncthreads();
        {
            float a0 = 0.f, a1 = 0.f;
#pragma unroll 4
            for (int tt = 0; tt < TENC; tt++) {
                float al = alpha[dg * TENC + tt];
                float2 f2 = *(const float2*)(fp + (size_t)tt * HD);
                a0 += al * f2.x; a1 += al * f2.y;
            }
            ipT[dg * KPD + dj] = a0;
            ipT[dg * KPD + dj + 1] = a1;
        }
        __syncthreads();
        gates_gemm5<KPD>(g_W2d, bias, ipT, gates, pg, tid);
        __syncthreads();
        for (int idx = tid; idx < G * HD; idx += NTH) {
            int g = idx >> 7, j = idx & 127;
            float gi = gates[g * NG + j];
            float gf = gates[g * NG + HD + j];
            float gg = gates[g * NG + 2 * HD + j];
            float go = gates[g * NG + 3 * HD + j];
            float c  = hcT[(128 + j) * HCT_STR + g];
            float c2 = siga(gf) * c + siga(gi) * tanha(gg);
            float h  = siga(go) * tanha(c2);
            hcT[j * HCT_STR + g] = h;
            hcT[(128 + j) * HCT_STR + g] = c2;
            ipT[g * KPD + HD + j] = h;
        }
        __syncthreads();
        if (sd >= DSTEPS - TDEC && wid < G) {
            float a = 0.f;
#pragma unroll
            for (int r = 0; r < 4; r++)
                a += hcT[(lane + 32 * r) * HCT_STR + wid] * vreg[lane + 32 * r];
#pragma unroll
            for (int o = 16; o; o >>= 1) a += __shfl_xor_sync(0xffffffffu, a, o);
            if (lane == 0)
                out[(size_t)(bid * G + wid) * TDEC + (sd - (DSTEPS - TDEC))] = a + vreg[130];
        }
    }
}

// ---------------- launch ----------------
extern "C" void kernel_launch(void* const* d_in, const int* in_sizes, int n_in,
                              void* d_out, int out_size) {
    const float* input_p_q = (const float*)d_in[0];
    const float* label_p   = (const float*)d_in[1];
    const float* Ue1_W = (const float*)d_in[2];
    const float* Ue1_b = (const float*)d_in[3];
    const float* We1_W = (const float*)d_in[4];
    const float* Ve1_W = (const float*)d_in[5];
    const float* Ve1_b = (const float*)d_in[6];
    const float* Ue2_W = (const float*)d_in[7];
    const float* Ue2_b = (const float*)d_in[8];
    const float* We2_W = (const float*)d_in[9];
    const float* Ve2_W = (const float*)d_in[10];
    const float* Ve2_b = (const float*)d_in[11];
    const float* Ud_W  = (const float*)d_in[12];
    const float* Ud_b  = (const float*)d_in[13];
    const float* Wd_W  = (const float*)d_in[14];
    const float* Vd_W  = (const float*)d_in[15];
    const float* Vd_b  = (const float*)d_in[16];
    const float* e1_Wih = (const float*)d_in[17];
    const float* e1_Whh = (const float*)d_in[18];
    const float* e1_bih = (const float*)d_in[19];
    const float* e1_bhh = (const float*)d_in[20];
    const float* e2_Wih = (const float*)d_in[21];
    const float* e2_Whh = (const float*)d_in[22];
    const float* e2_bih = (const float*)d_in[23];
    const float* e2_bhh = (const float*)d_in[24];
    const float* d_Wih  = (const float*)d_in[25];
    const float* d_Whh  = (const float*)d_in[26];
    const float* d_bih  = (const float*)d_in[27];
    const float* d_bhh  = (const float*)d_in[28];
    const float* reg_W  = (const float*)d_in[29];
    const float* reg_b  = (const float*)d_in[30];
    float* out = (float*)d_out;

    unsigned *p_W21, *p_W22;
    float *p_Wet1, *p_Wet2;
    float *p_b1, *p_b2, *p_pre1, *p_mid, *p_fin;
    cudaGetSymbolAddress((void**)&p_W21, g_W21);
    cudaGetSymbolAddress((void**)&p_W22, g_W22);
    cudaGetSymbolAddress((void**)&p_Wet1, g_Wet1);
    cudaGetSymbolAddress((void**)&p_Wet2, g_Wet2);
    cudaGetSymbolAddress((void**)&p_b1, g_b1);
    cudaGetSymbolAddress((void**)&p_b2, g_b2);
    cudaGetSymbolAddress((void**)&p_pre1, g_pre1);
    cudaGetSymbolAddress((void**)&p_mid, g_mid);
    cudaGetSymbolAddress((void**)&p_fin, g_fin);

    const int S1_FL = 12288 + (G*TENC*NF1) + (G*TENC*NF1) + 2560 + 384
                      + 1056 + 1056 + KP1 * 8 + 4096 + 4608 + 512 + 136;
    const int S2_FL = 12288 + (G*TENC*NF2/2) + 2560 + 384
                      + 1056 + 1056 + KP2 * 8 + 4096 + 4608 + 512 + 136;
    const int STAGE1_SMEM = S1_FL * 4;
    const int STAGE2_SMEM = S2_FL * 4;
    const int DEC_SMEM    = DEC_SMEM_FL * 4;
    const int UD_SMEM     = (16384 + TENC * 129) * 4;

    cudaFuncSetAttribute((const void*)stage_kernel<KP1, NF1, XH1, false>,
                         cudaFuncAttributeMaxDynamicSharedMemorySize, STAGE1_SMEM);
    cudaFuncSetAttribute((const void*)stage_kernel<KP2, NF2, XH2, true>,
                         cudaFuncAttributeMaxDynamicSharedMemorySize, STAGE2_SMEM);
    cudaFuncSetAttribute((const void*)decoder_kernel,
                         cudaFuncAttributeMaxDynamicSharedMemorySize, DEC_SMEM);
    cudaFuncSetAttribute((const void*)ud_kernel,
                         cudaFuncAttributeMaxDynamicSharedMemorySize, UD_SMEM);

    nop_kernel<<<1, 32>>>();   // keeps ncu capture slot on stage1
    setup_kernel<<<128, 256>>>(e1_Wih, e1_Whh, e2_Wih, e2_Whh, d_Wih, d_Whh,
                               We1_W, We2_W, Wd_W, Ud_W,
                               e1_bih, e1_bhh, e2_bih, e2_bhh, d_bih, d_bhh);
    pre1_kernel<<<BTOT, 256>>>(input_p_q, label_p, Ue1_W, Ue1_b);
    stage_kernel<KP1, NF1, XH1, false><<<NCTA, NTH, STAGE1_SMEM>>>(
        input_p_q, Ve1_W, Ve1_b, p_W21, p_b1, p_Wet1, p_pre1, p_mid, NF2);
    pre2_kernel<<<BTOT, 256>>>(Ue2_W, Ue2_b);
    stage_kernel<KP2, NF2, XH2, true><<<NCTA, NTH, STAGE2_SMEM>>>(
        input_p_q, Ve2_W, Ve2_b, p_W22, p_b2, p_Wet2, nullptr, p_fin, HD);
    ud_kernel<<<BTOT, 256, UD_SMEM>>>(Ud_b);
    decoder_kernel<<<NCTA, NTH, DEC_SMEM>>>(Vd_W, Vd_b, reg_W, reg_b, out);
}